// round 15
// baseline (speedup 1.0000x reference)
#include <cuda_runtime.h>
#include <cuda_fp16.h>
#include <math.h>

// ---------------- problem constants ----------------
#define NN   512
#define BB   64
#define LL   12
#define HH   12
#define RNN  64
#define DDEC 128
#define KENC 390
#define KDEC 804
#define SECE 416
#define SECD 832
#define KPE  (2*SECE)   // 832
#define KPD  (2*SECD)   // 1664
#define KGC  (2*NN)     // 1024
#define ROWS (NN*BB)    // 32768
#define NHBD (BB*DDEC+64) // 8256: dec hB width (h cols + 64 go cols)

// bgemm pipeline: 5 stages of As(128x40 hf) + Bs(32x136 hf) -> 94720 B, 2 CTA/SM
#define AS_ELEMS (128*40)
#define BS_ELEMS (32*136)
#define NSTAGE   5
#define SMEM_BYTES (NSTAGE * (AS_ELEMS + BS_ELEMS) * 2)   // 94720

typedef __half hf;

// ---------------- scratch (device globals; zero-init, no allocation) ----------------
__device__ float g_S[4*NN*NN];
__device__ float g_e1[NN*64];
__device__ float g_e2[NN*64];
__device__ float g_xT[NN*LL*BB];
__device__ float g_GX[4*NN*LL*BB];
__device__ float g_henc[ROWS*RNN];
__device__ float g_hdec[ROWS*DDEC];
__device__ float g_z [ROWS*DDEC];
__device__ float g_r [ROWS*DDEC];
__device__ float g_hc[ROWS*DDEC];
__device__ float g_go[ROWS];
// fp16 2-term split operands. B stored ONCE (K rows); bgemm wraps k>=Kp/2.
__device__ hf g_Sbig [4*NN*KGC];       // A: [hi|lo], 2048 x 1024
__device__ hf g_hB   [NN*NHBD];        // B: hi only, 512 x 8256 max
__device__ hf g_xgE  [ROWS*KPE];
__device__ hf g_xgD  [ROWS*KPD];
__device__ hf g_egWB [SECE*128];
__device__ hf g_euWB [SECE*64];
__device__ hf g_dgWB [SECD*256];
__device__ hf g_duWB [SECD*128];

// ---------------- helpers ----------------
__device__ __forceinline__ void split2h(float v, hf &h, hf &l) {
    h = __float2half(v);
    l = __float2half(v - __half2float(h));
}
__device__ __forceinline__ void store2(hf* p, int off, int sec, float v) {
    hf h, l; split2h(v, h, l);
    p[off] = h; p[sec + off] = l;
}
__device__ __forceinline__ void fma2(unsigned long long &d, unsigned long long a, unsigned long long b) {
    asm("fma.rn.f32x2 %0, %1, %2, %0;" : "+l"(d) : "l"(a), "l"(b));
}
__device__ __forceinline__ unsigned long long bcast2(float x) {
    unsigned long long r;
    asm("mov.b64 %0, {%1, %1};" : "=l"(r) : "f"(x));
    return r;
}
__device__ __forceinline__ void cpa16(void* s, const void* g, bool ok) {
    unsigned sa = (unsigned)__cvta_generic_to_shared(s);
    int sz = ok ? 16 : 0;
    asm volatile("cp.async.cg.shared.global [%0], [%1], 16, %2;"
                 :: "r"(sa), "l"(g), "r"(sz));
}

// ================= fp16 tensor-core GEMM, 128x128x32, 5-stage cp.async ==========
// Single __syncthreads per K-tile; issue after compute targets stage (kt-1)%5,
// drained by this iteration's barrier. B stored once (Kp/2 rows), row wraps.
// __launch_bounds__(256,2): force <=128 regs so 2 CTAs/SM is guaranteed.
// MODE 2: v=sigmoid(acc+bias[c]); c<splitN -> Cz else Cr
// MODE 3: C[r*ldC+c] = tanh(acc+bias[c])
// MODE 4: conv scatter into xg pairs. splitN = go-column boundary (0 = none).
template<int MODE>
__global__ void __launch_bounds__(256, 2)
bgemm(const hf* __restrict__ A, const hf* __restrict__ Bm, void* __restrict__ Cv,
      int M, int N, int Kp, const float* __restrict__ bias, float* __restrict__ C2,
      int splitN, int ldC, int hdshift, int sec, int o0, int o1, int o2, int o3)
{
    extern __shared__ __align__(16) char smem_raw[];
    hf* AsBase = (hf*)smem_raw;
    hf* BsBase = (hf*)smem_raw + NSTAGE * AS_ELEMS;

    const int tid  = threadIdx.x;
    const int lane = tid & 31;
    const int warp = tid >> 5;
    const int wm   = warp & 1;
    const int wn   = warp >> 1;
    const int row0 = blockIdx.y * 128;
    const int col0 = blockIdx.x * 128;
    const int Khalf = Kp >> 1;

    float acc[4][4][4];
    #pragma unroll
    for (int i = 0; i < 4; i++)
        #pragma unroll
        for (int j = 0; j < 4; j++)
            #pragma unroll
            for (int g = 0; g < 4; g++) acc[i][j][g] = 0.f;

    const int aq0 = tid * 2;
    const int ar0 = aq0 >> 2, ac0 = (aq0 & 3) * 8;
    const int ar1 = (aq0 + 1) >> 2, ac1 = ((aq0 + 1) & 3) * 8;
    const int br0 = aq0 >> 4, bc0 = (aq0 & 15) * 8;
    const int br1 = (aq0 + 1) >> 4, bc1 = ((aq0 + 1) & 15) * 8;
    const bool ok0 = (col0 + bc0) < N;
    const bool ok1 = (col0 + bc1) < N;

    const int T = Kp >> 5;

    #define ISSUE(s, kt) do {                                                          \
        hf* As_ = AsBase + (s) * AS_ELEMS;                                             \
        hf* Bs_ = BsBase + (s) * BS_ELEMS;                                             \
        const int k0_ = (kt) * 32;                                                     \
        int kr0_ = k0_ + br0; if (kr0_ >= Khalf) kr0_ -= Khalf;                        \
        int kr1_ = k0_ + br1; if (kr1_ >= Khalf) kr1_ -= Khalf;                        \
        cpa16(&As_[ar0 * 40 + ac0], A + (size_t)(row0 + ar0) * Kp + k0_ + ac0, true);  \
        cpa16(&As_[ar1 * 40 + ac1], A + (size_t)(row0 + ar1) * Kp + k0_ + ac1, true);  \
        cpa16(&Bs_[br0 * 136 + bc0],                                                   \
              ok0 ? (Bm + (size_t)kr0_ * N + col0 + bc0) : Bm, ok0);                   \
        cpa16(&Bs_[br1 * 136 + bc1],                                                   \
              ok1 ? (Bm + (size_t)kr1_ * N + col0 + bc1) : Bm, ok1);                   \
    } while (0)

    #pragma unroll
    for (int s = 0; s < NSTAGE - 1; s++) {
        if (s < T) ISSUE(s, s);
        asm volatile("cp.async.commit_group;");
    }

    for (int kt = 0; kt < T; kt++) {
        asm volatile("cp.async.wait_group %0;" :: "n"(NSTAGE - 2));
        __syncthreads();

        const int cur = kt % NSTAGE;
        const hf* As = AsBase + cur * AS_ELEMS;
        const hf* Bs = BsBase + cur * BS_ELEMS;
        #pragma unroll
        for (int kk = 0; kk < 2; kk++) {
            unsigned af[4][4], bfg[4][2];
            #pragma unroll
            for (int i = 0; i < 4; i++) {
                const hf* p = &As[(wm * 64 + i * 16 + (lane & 15)) * 40 + kk * 16 + (lane >> 4) * 8];
                unsigned addr = (unsigned)__cvta_generic_to_shared(p);
                asm volatile("ldmatrix.sync.aligned.m8n8.x4.shared.b16 {%0,%1,%2,%3}, [%4];"
                             : "=r"(af[i][0]), "=r"(af[i][1]), "=r"(af[i][2]), "=r"(af[i][3])
                             : "r"(addr));
            }
            #pragma unroll
            for (int j = 0; j < 4; j++) {
                const hf* p = &Bs[(kk * 16 + (lane & 15)) * 136 + wn * 32 + j * 8];
                unsigned addr = (unsigned)__cvta_generic_to_shared(p);
                asm volatile("ldmatrix.sync.aligned.m8n8.x2.trans.shared.b16 {%0,%1}, [%2];"
                             : "=r"(bfg[j][0]), "=r"(bfg[j][1]) : "r"(addr));
            }
            #pragma unroll
            for (int i = 0; i < 4; i++)
                #pragma unroll
                for (int j = 0; j < 4; j++)
                    asm volatile(
                        "mma.sync.aligned.m16n8k16.row.col.f32.f16.f16.f32 "
                        "{%0,%1,%2,%3}, {%4,%5,%6,%7}, {%8,%9}, {%0,%1,%2,%3};"
                        : "+f"(acc[i][j][0]), "+f"(acc[i][j][1]), "+f"(acc[i][j][2]), "+f"(acc[i][j][3])
                        : "r"(af[i][0]), "r"(af[i][1]), "r"(af[i][2]), "r"(af[i][3]),
                          "r"(bfg[j][0]), "r"(bfg[j][1]));
        }

        if (kt + NSTAGE - 1 < T) ISSUE((kt + NSTAGE - 1) % NSTAGE, kt + NSTAGE - 1);
        asm volatile("cp.async.commit_group;");
    }
    #undef ISSUE

    // epilogue
    if (MODE == 4) {
        hf* C = (hf*)Cv;
        const int jblk = row0 >> 9;
        const int off  = (jblk == 0) ? o0 : (jblk == 1) ? o1 : (jblk == 2) ? o2 : o3;
        const int goff = (jblk == 0) ? 134 : (jblk == 1) ? 268 : (jblk == 2) ? 536 : 670;
        const int hmask = (1 << hdshift) - 1;
        const int Ktot = 2 * sec;
        #pragma unroll
        for (int i = 0; i < 4; i++)
            #pragma unroll
            for (int j = 0; j < 4; j++)
                #pragma unroll
                for (int g = 0; g < 4; g++) {
                    int rr = row0 + wm * 64 + i * 16 + (lane >> 2) + ((g >> 1) << 3);
                    int cc = col0 + wn * 32 + j * 8 + ((lane & 3) << 1) + (g & 1);
                    if (cc >= N) continue;
                    int n = rr & (NN - 1);
                    float v = acc[i][j][g];
                    if (splitN && cc >= splitN) {
                        int b = cc - splitN;
                        store2(C + (size_t)(n * BB + b) * Ktot, goff, sec, v);
                    } else {
                        int b = cc >> hdshift;
                        int c = cc & hmask;
                        store2(C + (size_t)(n * BB + b) * Ktot, off + c, sec, v);
                    }
                }
    } else {
        float* C = (float*)Cv;
        #pragma unroll
        for (int i = 0; i < 4; i++)
            #pragma unroll
            for (int j = 0; j < 4; j++)
                #pragma unroll
                for (int g = 0; g < 4; g++) {
                    int rr = row0 + wm * 64 + i * 16 + (lane >> 2) + ((g >> 1) << 3);
                    int cc = col0 + wn * 32 + j * 8 + ((lane & 3) << 1) + (g & 1);
                    if (cc >= N) continue;
                    float v = acc[i][j][g];
                    if (MODE == 2) {
                        v = 1.f / (1.f + expf(-(v + bias[cc])));
                        if (cc < splitN) C [(size_t)rr * splitN + cc]            = v;
                        else             C2[(size_t)rr * splitN + (cc - splitN)] = v;
                    } else { // MODE 3
                        C[(size_t)rr * ldC + cc] = tanhf(v + bias[cc]);
                    }
                }
    }
}

// ================= fp32 f32x2 SGEMM (setup GEMMs only) =====================
template<int MODE>   // MODE 0: plain, MODE 1: 2*acc - I
__global__ void __launch_bounds__(256)
sgemm(const float* __restrict__ A, const float* __restrict__ Bm, float* __restrict__ C,
      int M, int N, int K)
{
    __shared__ __align__(16) float As[2][16][132];
    __shared__ __align__(16) float Bsh[2][16][132];
    const int tid = threadIdx.x;
    const int tx  = tid & 15;
    const int ty  = tid >> 4;
    const int row0 = blockIdx.y * 128;
    const int col0 = blockIdx.x * 128;

    const int am  = tid >> 1;
    const int ak0 = (tid & 1) << 2;
    const int bk  = tid >> 5;
    const int bn  = (tid & 31) << 2;
    const int gn  = col0 + bn;
    const bool bok = gn < N;

    unsigned long long acc[8][4];
    #pragma unroll
    for (int i = 0; i < 8; i++)
        #pragma unroll
        for (int j = 0; j < 4; j++) acc[i][j] = 0ull;

    const int T = K >> 4;
    const float4 z4 = make_float4(0.f, 0.f, 0.f, 0.f);
    const float* Abase = A + (size_t)(row0 + am) * K + ak0;

    float4 ra0 = *(const float4*)(Abase);
    float4 ra1 = *(const float4*)(Abase + 8);
    float4 rb0 = bok ? *(const float4*)(Bm + (size_t)bk * N + gn) : z4;
    float4 rb1 = bok ? *(const float4*)(Bm + (size_t)(bk + 8) * N + gn) : z4;
    As[0][ak0 + 0][am] = ra0.x; As[0][ak0 + 1][am] = ra0.y;
    As[0][ak0 + 2][am] = ra0.z; As[0][ak0 + 3][am] = ra0.w;
    As[0][ak0 + 8][am] = ra1.x; As[0][ak0 + 9][am] = ra1.y;
    As[0][ak0 +10][am] = ra1.z; As[0][ak0 +11][am] = ra1.w;
    *(float4*)&Bsh[0][bk][bn]     = rb0;
    *(float4*)&Bsh[0][bk + 8][bn] = rb1;
    __syncthreads();

    for (int kt = 0; kt < T; kt++) {
        const int cur = kt & 1;
        if (kt + 1 < T) {
            const float* Ap = Abase + (kt + 1) * 16;
            ra0 = *(const float4*)(Ap);
            ra1 = *(const float4*)(Ap + 8);
            const int gk = (kt + 1) * 16;
            rb0 = bok ? *(const float4*)(Bm + (size_t)(gk + bk) * N + gn) : z4;
            rb1 = bok ? *(const float4*)(Bm + (size_t)(gk + bk + 8) * N + gn) : z4;
        }
        #pragma unroll
        for (int kk = 0; kk < 16; kk++) {
            float4 a0 = *(const float4*)&As[cur][kk][ty * 8];
            float4 a1 = *(const float4*)&As[cur][kk][ty * 8 + 4];
            ulonglong2 bp0 = *(const ulonglong2*)&Bsh[cur][kk][tx * 8];
            ulonglong2 bp1 = *(const ulonglong2*)&Bsh[cur][kk][tx * 8 + 4];
            unsigned long long b2[4] = { bp0.x, bp0.y, bp1.x, bp1.y };
            unsigned long long a2[8] = {
                bcast2(a0.x), bcast2(a0.y), bcast2(a0.z), bcast2(a0.w),
                bcast2(a1.x), bcast2(a1.y), bcast2(a1.z), bcast2(a1.w)
            };
            #pragma unroll
            for (int i = 0; i < 8; i++)
                #pragma unroll
                for (int j = 0; j < 4; j++)
                    fma2(acc[i][j], a2[i], b2[j]);
        }
        if (kt + 1 < T) {
            const int nxt = cur ^ 1;
            As[nxt][ak0 + 0][am] = ra0.x; As[nxt][ak0 + 1][am] = ra0.y;
            As[nxt][ak0 + 2][am] = ra0.z; As[nxt][ak0 + 3][am] = ra0.w;
            As[nxt][ak0 + 8][am] = ra1.x; As[nxt][ak0 + 9][am] = ra1.y;
            As[nxt][ak0 +10][am] = ra1.z; As[nxt][ak0 +11][am] = ra1.w;
            *(float4*)&Bsh[nxt][bk][bn]     = rb0;
            *(float4*)&Bsh[nxt][bk + 8][bn] = rb1;
        }
        __syncthreads();
    }

    #pragma unroll
    for (int i = 0; i < 8; i++) {
        const int rrow = row0 + ty * 8 + i;
        #pragma unroll
        for (int j = 0; j < 4; j++) {
            #pragma unroll
            for (int h = 0; h < 2; h++) {
                const int cc = col0 + tx * 8 + 2 * j + h;
                if (cc >= N) continue;
                float v = h ? __uint_as_float((unsigned)(acc[i][j] >> 32))
                            : __uint_as_float((unsigned)(acc[i][j]));
                if (MODE == 0) C[(size_t)rrow * N + cc] = v;
                else           C[(size_t)rrow * N + cc] = 2.f * v - ((rrow == cc) ? 1.f : 0.f);
            }
        }
    }
}

// ---------------- small kernels ----------------
__global__ void k_zero(float* p, int n) {
    int i = blockIdx.x * blockDim.x + threadIdx.x;
    if (i < n) p[i] = 0.f;
}

__global__ void k_splitA(const float* __restrict__ in, hf* __restrict__ out, int K, int total) {
    int i = blockIdx.x * blockDim.x + threadIdx.x;
    if (i >= total) return;
    int m = i / K, k = i - m * K;
    hf h, l; split2h(in[i], h, l);
    hf* p = out + (size_t)m * 2 * K;
    p[k] = h; p[K + k] = l;
}

__global__ void k_packB(const float* __restrict__ in, hf* __restrict__ out, int total) {
    int i = blockIdx.x * blockDim.x + threadIdx.x;
    if (i < total) out[i] = __float2half(in[i]);
}

__global__ void k_packB_dec(const float* __restrict__ in, hf* __restrict__ out) {
    int i = blockIdx.x * blockDim.x + threadIdx.x;
    if (i >= ROWS * DDEC) return;
    int row = i >> 7, c = i & 127;
    int n = row >> 6, b = row & 63;
    out[(size_t)n * NHBD + b * DDEC + c] = __float2half(in[i]);
}
__global__ void k_zero_go(hf* __restrict__ hB) {
    int i = blockIdx.x * blockDim.x + threadIdx.x;
    if (i >= NN * BB) return;
    int n = i >> 6, b = i & 63;
    hB[(size_t)n * NHBD + BB * DDEC + b] = __float2half(0.f);
}

__global__ void k_eW(const float* __restrict__ We, const float* __restrict__ Mem,
                     float* __restrict__ e) {
    int idx = blockIdx.x * blockDim.x + threadIdx.x;
    if (idx >= NN * 64) return;
    int n = idx >> 6, d = idx & 63;
    float s = 0.f;
    #pragma unroll
    for (int k = 0; k < 20; k++) s += We[n * 20 + k] * Mem[k * 64 + d];
    e[idx] = s;
}

__global__ void k_gsoftmax(const float* __restrict__ ea, const float* __restrict__ eb,
                           float* __restrict__ g) {
    __shared__ float er[64];
    __shared__ float buf[NN];
    __shared__ float red[128];
    int n = blockIdx.x, tid = threadIdx.x;
    if (tid < 64) er[tid] = ea[n * 64 + tid];
    __syncthreads();
    for (int m = tid; m < NN; m += 128) {
        float s = 0.f;
        #pragma unroll
        for (int d = 0; d < 64; d++) s += er[d] * eb[m * 64 + d];
        buf[m] = s > 0.f ? s : 0.f;
    }
    __syncthreads();
    float mx = -1e30f;
    for (int m = tid; m < NN; m += 128) mx = fmaxf(mx, buf[m]);
    red[tid] = mx; __syncthreads();
    for (int s = 64; s > 0; s >>= 1) { if (tid < s) red[tid] = fmaxf(red[tid], red[tid + s]); __syncthreads(); }
    mx = red[0]; __syncthreads();
    float sm = 0.f;
    for (int m = tid; m < NN; m += 128) { float e = expf(buf[m] - mx); buf[m] = e; sm += e; }
    red[tid] = sm; __syncthreads();
    for (int s = 64; s > 0; s >>= 1) { if (tid < s) red[tid] += red[tid + s]; __syncthreads(); }
    float inv = 1.f / red[0];
    for (int m = tid; m < NN; m += 128) g[n * NN + m] = buf[m] * inv;
}

__global__ void k_xT(const float* __restrict__ x, float* __restrict__ xT) {
    int idx = blockIdx.x * blockDim.x + threadIdx.x;
    if (idx >= BB * NN * LL) return;
    int l = idx % LL;
    int n = (idx / LL) % NN;
    int b = idx / (LL * NN);
    xT[(n * LL + l) * BB + b] = x[idx];
}

__global__ void k_fill_enc_x(hf* __restrict__ xg, const float* __restrict__ xT,
                             const float* __restrict__ GX, int l) {
    int row = blockIdx.x * blockDim.x + threadIdx.x;
    if (row >= ROWS) return;
    int n = row >> 6, b = row & 63;
    hf* p = xg + (size_t)row * KPE;
    float xv = xT[(n * LL + l) * BB + b];
    store2(p, 0, SECE, xv);
    store2(p, 195, SECE, xv);
    store2(p, 65,  SECE, GX[(size_t)(0 * NN + n) * (LL * BB) + l * BB + b]);
    store2(p, 130, SECE, GX[(size_t)(1 * NN + n) * (LL * BB) + l * BB + b]);
    store2(p, 260, SECE, GX[(size_t)(2 * NN + n) * (LL * BB) + l * BB + b]);
    store2(p, 325, SECE, GX[(size_t)(3 * NN + n) * (LL * BB) + l * BB + b]);
}

__global__ void k_fill_h_id(hf* __restrict__ xg, const float* __restrict__ h,
                            int hdshift, int sec, int off0, int off3, int total) {
    int i = blockIdx.x * blockDim.x + threadIdx.x;
    if (i >= total) return;
    int row = i >> hdshift;
    int c   = i & ((1 << hdshift) - 1);
    float v = h[i];
    hf* p = xg + (size_t)row * 2 * sec;
    store2(p, off0 + c, sec, v);
    store2(p, off3 + c, sec, v);
}

// FUSED (2/thread): zh = z*h -> xg id-blocks + hB (half2, width Ncols)
__global__ void k_zh_pack(const float* __restrict__ z, const float* __restrict__ h,
                          hf* __restrict__ xg, hf* __restrict__ hB,
                          int hdshift, int sec, int off0, int off3, int Ncols, int total2) {
    int i = blockIdx.x * blockDim.x + threadIdx.x;
    if (i >= total2) return;
    int base = i * 2;
    int row = base >> hdshift;
    int c   = base & ((1 << hdshift) - 1);
    float2 zv = *(const float2*)(z + base);
    float2 hv = *(const float2*)(h + base);
    float v0 = zv.x * hv.x, v1 = zv.y * hv.y;
    hf* p = xg + (size_t)row * 2 * sec;
    store2(p, off0 + c, sec, v0);     store2(p, off0 + c + 1, sec, v1);
    store2(p, off3 + c, sec, v0);     store2(p, off3 + c + 1, sec, v1);
    int n = row >> 6, b = row & 63;
    __half2 hv2 = __floats2half2_rn(v0, v1);
    *(__half2*)(hB + (size_t)n * Ncols + ((size_t)b << hdshift) + c) = hv2;
}

// FUSED (2/thread): h' = r*h+(1-r)*hc -> h, xg id-blocks, hB (encoder)
__global__ void k_hupd_pack(const float* __restrict__ r, const float* __restrict__ hc,
                            float* __restrict__ h,
                            hf* __restrict__ xg, hf* __restrict__ hB,
                            int hdshift, int sec, int off0, int off3, int Ncols, int total2) {
    int i = blockIdx.x * blockDim.x + threadIdx.x;
    if (i >= total2) return;
    int base = i * 2;
    int row = base >> hdshift;
    int c   = base & ((1 << hdshift) - 1);
    float2 rv = *(const float2*)(r + base);
    float2 hcv = *(const float2*)(hc + base);
    float2 hv = *(const float2*)(h + base);
    float hn0 = rv.x * hv.x + (1.f - rv.x) * hcv.x;
    float hn1 = rv.y * hv.y + (1.f - rv.y) * hcv.y;
    *(float2*)(h + base) = make_float2(hn0, hn1);
    hf* p = xg + (size_t)row * 2 * sec;
    store2(p, off0 + c, sec, hn0);    store2(p, off0 + c + 1, sec, hn1);
    store2(p, off3 + c, sec, hn0);    store2(p, off3 + c + 1, sec, hn1);
    int n = row >> 6, b = row & 63;
    __half2 hv2 = __floats2half2_rn(hn0, hn1);
    *(__half2*)(hB + (size_t)n * Ncols + ((size_t)b << hdshift) + c) = hv2;
}

// fill decoder go-id + ycov channels for step t (go-conv channels come from bgemm)
__global__ void k_fill_dec(hf* __restrict__ xg, const float* __restrict__ go,
                           const float* __restrict__ tt, int t) {
    int row = blockIdx.x * blockDim.x + threadIdx.x;
    if (row >= ROWS) return;
    int b = row & 63;
    hf* p = xg + (size_t)row * KPD;
    float gv = go[row];
    store2(p, 0,   SECD, gv);
    store2(p, 402, SECD, gv);
    #pragma unroll
    for (int c = 0; c < 5; c++) {
        float v = tt[(b * 5 + c) * HH + t];
        store2(p, 1 + c,   SECD, v); store2(p, 135 + c, SECD, v);
        store2(p, 269 + c, SECD, v); store2(p, 403 + c, SECD, v);
        store2(p, 537 + c, SECD, v); store2(p, 671 + c, SECD, v);
    }
}

__global__ void k_attn(const float* __restrict__ h, const float* __restrict__ Wq,
                       const float* __restrict__ Mem, float* __restrict__ hde) {
    __shared__ float hr[64];
    __shared__ float q[64];
    __shared__ float sc[20];
    int row = blockIdx.x, tid = threadIdx.x;
    hr[tid] = h[row * 64 + tid];
    __syncthreads();
    float s = 0.f;
    #pragma unroll
    for (int c = 0; c < 64; c++) s += hr[c] * Wq[c * 64 + tid];
    q[tid] = s;
    __syncthreads();
    if (tid < 20) {
        float v = 0.f;
        #pragma unroll
        for (int c = 0; c < 64; c++) v += q[c] * Mem[tid * 64 + c];
        sc[tid] = v;
    }
    __syncthreads();
    if (tid == 0) {
        float mx = -1e30f;
        for (int j = 0; j < 20; j++) mx = fmaxf(mx, sc[j]);
        float sm = 0.f;
        for (int j = 0; j < 20; j++) { sc[j] = expf(sc[j] - mx); sm += sc[j]; }
        float inv = 1.f / sm;
        for (int j = 0; j < 20; j++) sc[j] *= inv;
    }
    __syncthreads();
    float ha = 0.f;
    #pragma unroll
    for (int j = 0; j < 20; j++) ha += sc[j] * Mem[j * 64 + tid];
    hde[row * 128 + tid]      = hr[tid];
    hde[row * 128 + 64 + tid] = ha;
}

// FUSED decoder h update + pack + projection + go write; 64 thr/row, 2 c/thread
__global__ void k_hupd_dec_pack(const float* __restrict__ r, const float* __restrict__ hc,
                                float* __restrict__ h, const float* __restrict__ pW,
                                const float* __restrict__ pb, float* __restrict__ go,
                                float* __restrict__ out, int t,
                                hf* __restrict__ xg, hf* __restrict__ hB) {
    __shared__ float red[64];
    int row = blockIdx.x, tid = threadIdx.x;
    int c = tid * 2;
    int i = row * 128 + c;
    float2 rv = *(const float2*)(r + i);
    float2 hcv = *(const float2*)(hc + i);
    float2 hv = *(const float2*)(h + i);
    float hn0 = rv.x * hv.x + (1.f - rv.x) * hcv.x;
    float hn1 = rv.y * hv.y + (1.f - rv.y) * hcv.y;
    *(float2*)(h + i) = make_float2(hn0, hn1);
    hf* p = xg + (size_t)row * KPD;
    store2(p, 6 + c, SECD, hn0);   store2(p, 6 + c + 1, SECD, hn1);
    store2(p, 408 + c, SECD, hn0); store2(p, 408 + c + 1, SECD, hn1);
    int n = row >> 6, b = row & 63;
    __half2 hv2 = __floats2half2_rn(hn0, hn1);
    *(__half2*)(hB + (size_t)n * NHBD + b * DDEC + c) = hv2;
    float2 pw = *(const float2*)(pW + c);
    red[tid] = hn0 * pw.x + hn1 * pw.y;
    __syncthreads();
    for (int s = 32; s > 0; s >>= 1) { if (tid < s) red[tid] += red[tid + s]; __syncthreads(); }
    if (tid == 0) {
        float g = red[0] + pb[0];
        go[row] = g;
        out[(b * NN + n) * HH + t] = g;
        hB[(size_t)n * NHBD + BB * DDEC + b] = __float2half(g);   // go column for next conv
    }
}

// ---------------- host side ----------------
static void bgemm_launch(int mode, const hf* A, const hf* B, void* C,
                         int M, int N, int Kp,
                         const float* bias = nullptr, float* C2 = nullptr,
                         int splitN = 0, int ldC = 0, int hdshift = 0, int sec = 0,
                         int o0 = 0, int o1 = 0, int o2 = 0, int o3 = 0)
{
    dim3 grid((N + 127) / 128, M / 128);
    switch (mode) {
        case 2: bgemm<2><<<grid, 256, SMEM_BYTES>>>(A, B, C, M, N, Kp, bias, C2, splitN, ldC, hdshift, sec, o0, o1, o2, o3); break;
        case 3: bgemm<3><<<grid, 256, SMEM_BYTES>>>(A, B, C, M, N, Kp, bias, C2, splitN, ldC, hdshift, sec, o0, o1, o2, o3); break;
        case 4: bgemm<4><<<grid, 256, SMEM_BYTES>>>(A, B, C, M, N, Kp, bias, C2, splitN, ldC, hdshift, sec, o0, o1, o2, o3); break;
    }
}

extern "C" void kernel_launch(void* const* d_in, const int* in_sizes, int n_in,
                              void* d_out, int out_size)
{
    const float* x   = (const float*)d_in[0];
    const float* tt  = (const float*)d_in[3];
    const float* Mem = (const float*)d_in[5];
    const float* Wq  = (const float*)d_in[6];
    const float* We1 = (const float*)d_in[7];
    const float* We2 = (const float*)d_in[8];
    const float* egW = (const float*)d_in[9];
    const float* egb = (const float*)d_in[10];
    const float* euW = (const float*)d_in[11];
    const float* eub = (const float*)d_in[12];
    const float* dgW = (const float*)d_in[13];
    const float* dgb = (const float*)d_in[14];
    const float* duW = (const float*)d_in[15];
    const float* dub = (const float*)d_in[16];
    const float* pW  = (const float*)d_in[17];
    const float* pb  = (const float*)d_in[18];
    float* out = (float*)d_out;

    cudaFuncSetAttribute(bgemm<2>, cudaFuncAttributeMaxDynamicSharedMemorySize, SMEM_BYTES);
    cudaFuncSetAttribute(bgemm<3>, cudaFuncAttributeMaxDynamicSharedMemorySize, SMEM_BYTES);
    cudaFuncSetAttribute(bgemm<4>, cudaFuncAttributeMaxDynamicSharedMemorySize, SMEM_BYTES);

    float *S, *e1, *e2, *xT, *GX, *henc, *hdec, *z, *r, *hc, *go;
    hf *Sbig, *hB, *xgE, *xgD, *egWB, *euWB, *dgWB, *duWB;
    cudaGetSymbolAddress((void**)&S,    g_S);
    cudaGetSymbolAddress((void**)&e1,   g_e1);
    cudaGetSymbolAddress((void**)&e2,   g_e2);
    cudaGetSymbolAddress((void**)&xT,   g_xT);
    cudaGetSymbolAddress((void**)&GX,   g_GX);
    cudaGetSymbolAddress((void**)&henc, g_henc);
    cudaGetSymbolAddress((void**)&hdec, g_hdec);
    cudaGetSymbolAddress((void**)&z,    g_z);
    cudaGetSymbolAddress((void**)&r,    g_r);
    cudaGetSymbolAddress((void**)&hc,   g_hc);
    cudaGetSymbolAddress((void**)&go,   g_go);
    cudaGetSymbolAddress((void**)&Sbig, g_Sbig);
    cudaGetSymbolAddress((void**)&hB,   g_hB);
    cudaGetSymbolAddress((void**)&xgE,  g_xgE);
    cudaGetSymbolAddress((void**)&xgD,  g_xgD);
    cudaGetSymbolAddress((void**)&egWB, g_egWB);
    cudaGetSymbolAddress((void**)&euWB, g_euWB);
    cudaGetSymbolAddress((void**)&dgWB, g_dgWB);
    cudaGetSymbolAddress((void**)&duWB, g_duWB);

    // --- weight packs ---
    k_packB<<<(KENC * 128 + 255) / 256, 256>>>(egW, egWB, KENC * 128);
    k_packB<<<(KENC * 64  + 255) / 256, 256>>>(euW, euWB, KENC * 64);
    k_packB<<<(KDEC * 256 + 255) / 256, 256>>>(dgW, dgWB, KDEC * 256);
    k_packB<<<(KDEC * 128 + 255) / 256, 256>>>(duW, duWB, KDEC * 128);

    // --- supports (fp32) ---
    k_eW<<<(NN * 64 + 255) / 256, 256>>>(We1, Mem, e1);
    k_eW<<<(NN * 64 + 255) / 256, 256>>>(We2, Mem, e2);
    k_gsoftmax<<<NN, 128>>>(e1, e2, S);
    k_gsoftmax<<<NN, 128>>>(e2, e1, S + 2 * NN * NN);
    {
        dim3 g1(NN / 128, NN / 128);
        sgemm<1><<<g1, 256>>>(S,               S,               S + 1 * NN * NN, NN, NN, NN);
        sgemm<1><<<g1, 256>>>(S + 2 * NN * NN, S + 2 * NN * NN, S + 3 * NN * NN, NN, NN, NN);
    }
    k_splitA<<<(4 * NN * NN + 255) / 256, 256>>>(S, Sbig, NN, 4 * NN * NN);

    // --- encoder x precompute (fp32) ---
    k_xT<<<(BB * NN * LL + 255) / 256, 256>>>(x, xT);
    {
        dim3 g2((LL * BB + 127) / 128, 4 * NN / 128);
        sgemm<0><<<g2, 256>>>(S, xT, GX, 4 * NN, LL * BB, NN);
    }

    // --- init states ---
    k_zero<<<(ROWS * RNN + 255) / 256, 256>>>(henc, ROWS * RNN);
    k_zero<<<(ROWS + 255) / 256, 256>>>(go, ROWS);
    k_fill_h_id<<<(ROWS * RNN) / 256, 256>>>(xgE, henc, 6, SECE, 1, 196, ROWS * RNN);
    k_packB<<<(ROWS * RNN + 255) / 256, 256>>>(henc, hB, ROWS * RNN);

    // --- encoder ---
    for (int l = 0; l < LL; l++) {
        k_fill_enc_x<<<ROWS / 256, 256>>>(xgE, xT, GX, l);
        bgemm_launch(4, Sbig, hB, xgE, 4 * NN, BB * RNN, KGC,
                     nullptr, nullptr, 0, 0, 6, SECE, 66, 131, 261, 326);
        bgemm_launch(2, xgE, egWB, z, ROWS, 2 * RNN, KPE, egb, r, RNN);
        k_zh_pack<<<(ROWS * RNN / 2) / 256, 256>>>(z, henc, xgE, hB, 6, SECE, 1, 196, BB * RNN, ROWS * RNN / 2);
        bgemm_launch(4, Sbig, hB, xgE, 4 * NN, BB * RNN, KGC,
                     nullptr, nullptr, 0, 0, 6, SECE, 66, 131, 261, 326);
        bgemm_launch(3, xgE, euWB, hc, ROWS, RNN, KPE, eub, nullptr, 0, RNN);
        k_hupd_pack<<<(ROWS * RNN / 2) / 256, 256>>>(r, hc, henc, xgE, hB, 6, SECE, 1, 196, BB * RNN, ROWS * RNN / 2);
    }

    // --- memory attention -> decoder initial hidden ---
    k_attn<<<ROWS, 64>>>(henc, Wq, Mem, hdec);
    k_fill_h_id<<<(ROWS * DDEC) / 256, 256>>>(xgD, hdec, 7, SECD, 6, 408, ROWS * DDEC);
    k_packB_dec<<<(ROWS * DDEC + 255) / 256, 256>>>(hdec, hB);
    k_zero_go<<<(NN * BB + 255) / 256, 256>>>(hB);

    // --- decoder ---
    for (int t = 0; t < HH; t++) {
        k_fill_dec<<<ROWS / 256, 256>>>(xgD, go, tt, t);
        // conv(h) + conv(go) fused (go cols at splitN = BB*DDEC)
        bgemm_launch(4, Sbig, hB, xgD, 4 * NN, NHBD, KGC,
                     nullptr, nullptr, BB * DDEC, 0, 7, SECD, 140, 274, 542, 676);
        bgemm_launch(2, xgD, dgWB, z, ROWS, 2 * DDEC, KPD, dgb, r, DDEC);
        k_zh_pack<<<(ROWS * DDEC / 2) / 256, 256>>>(z, hdec, xgD, hB, 7, SECD, 6, 408, NHBD, ROWS * DDEC / 2);
        bgemm_launch(4, Sbig, hB, xgD, 4 * NN, NHBD, KGC,
                     nullptr, nullptr, BB * DDEC, 0, 7, SECD, 140, 274, 542, 676);
        bgemm_launch(3, xgD, duWB, hc, ROWS, DDEC, KPD, dub, nullptr, 0, DDEC);
        k_hupd_dec_pack<<<ROWS, 64>>>(r, hc, hdec, pW, pb, go, out, t, xgD, hB);
    }
}

// round 16
// speedup vs baseline: 1.0403x; 1.0403x over previous
#include <cuda_runtime.h>
#include <cuda_fp16.h>
#include <math.h>

// ---------------- problem constants ----------------
#define NN   512
#define BB   64
#define LL   12
#define HH   12
#define RNN  64
#define DDEC 128
#define KENC 390
#define KDEC 804
#define SECE 416
#define SECD 832
#define KPE  (2*SECE)   // 832
#define KPD  (2*SECD)   // 1664
#define KGC  (2*NN)     // 1024
#define ROWS (NN*BB)    // 32768
#define NHBD (BB*DDEC+64) // 8256: dec hB width (h cols + 64 go cols)

// bgemm pipeline: 4 stages of As(128x40 hf) + Bs(32x136 hf) -> 75776 B, 2 CTA/SM
#define AS_ELEMS (128*40)
#define BS_ELEMS (32*136)
#define NSTAGE   4
#define SMEM_BYTES (NSTAGE * (AS_ELEMS + BS_ELEMS) * 2)   // 75776

typedef __half hf;

// ---------------- scratch (device globals; zero-init, no allocation) ----------------
__device__ float g_S[4*NN*NN];
__device__ float g_e1[NN*64];
__device__ float g_e2[NN*64];
__device__ float g_xT[NN*LL*BB];
__device__ float g_GX[4*NN*LL*BB];
__device__ float g_henc[ROWS*RNN];
__device__ float g_hdec[ROWS*DDEC];
__device__ float g_z [ROWS*DDEC];
__device__ float g_r [ROWS*DDEC];
__device__ float g_hc[ROWS*DDEC];
__device__ float g_go[ROWS];
// fp16 2-term split operands. B stored ONCE (K rows); bgemm wraps k>=Kp/2.
__device__ hf g_Sbig [4*NN*KGC];       // A: [hi|lo], 2048 x 1024
__device__ hf g_hB   [NN*NHBD];        // B: hi only, 512 x 8256 max
__device__ hf g_xgE  [ROWS*KPE];
__device__ hf g_xgD  [ROWS*KPD];
__device__ hf g_egWB [SECE*128];
__device__ hf g_euWB [SECE*64];
__device__ hf g_dgWB [SECD*256];
__device__ hf g_duWB [SECD*128];

// ---------------- helpers ----------------
__device__ __forceinline__ void split2h(float v, hf &h, hf &l) {
    h = __float2half(v);
    l = __float2half(v - __half2float(h));
}
__device__ __forceinline__ void store2(hf* p, int off, int sec, float v) {
    hf h, l; split2h(v, h, l);
    p[off] = h; p[sec + off] = l;
}
__device__ __forceinline__ void fma2(unsigned long long &d, unsigned long long a, unsigned long long b) {
    asm("fma.rn.f32x2 %0, %1, %2, %0;" : "+l"(d) : "l"(a), "l"(b));
}
__device__ __forceinline__ unsigned long long bcast2(float x) {
    unsigned long long r;
    asm("mov.b64 %0, {%1, %1};" : "=l"(r) : "f"(x));
    return r;
}
__device__ __forceinline__ void cpa16(void* s, const void* g, bool ok) {
    unsigned sa = (unsigned)__cvta_generic_to_shared(s);
    int sz = ok ? 16 : 0;
    asm volatile("cp.async.cg.shared.global [%0], [%1], 16, %2;"
                 :: "r"(sa), "l"(g), "r"(sz));
}

// ================= fp16 tensor-core GEMM, 128x128x32, 4-stage cp.async ==========
// Single __syncthreads per K-tile (R10/R14-proven). B stored once, row wraps.
// MODE 2: v=sigmoid(acc+bias[c]); c<splitN -> Cz else Cr
// MODE 3: C[r*ldC+c] = tanh(acc+bias[c])
// MODE 4: conv scatter into xg pairs. splitN = go-column boundary (0 = none).
template<int MODE>
__global__ void __launch_bounds__(256)
bgemm(const hf* __restrict__ A, const hf* __restrict__ Bm, void* __restrict__ Cv,
      int M, int N, int Kp, const float* __restrict__ bias, float* __restrict__ C2,
      int splitN, int ldC, int hdshift, int sec, int o0, int o1, int o2, int o3)
{
    extern __shared__ __align__(16) char smem_raw[];
    hf* AsBase = (hf*)smem_raw;
    hf* BsBase = (hf*)smem_raw + NSTAGE * AS_ELEMS;

    const int tid  = threadIdx.x;
    const int lane = tid & 31;
    const int warp = tid >> 5;
    const int wm   = warp & 1;
    const int wn   = warp >> 1;
    const int row0 = blockIdx.y * 128;
    const int col0 = blockIdx.x * 128;
    const int Khalf = Kp >> 1;

    float acc[4][4][4];
    #pragma unroll
    for (int i = 0; i < 4; i++)
        #pragma unroll
        for (int j = 0; j < 4; j++)
            #pragma unroll
            for (int g = 0; g < 4; g++) acc[i][j][g] = 0.f;

    const int aq0 = tid * 2;
    const int ar0 = aq0 >> 2, ac0 = (aq0 & 3) * 8;
    const int ar1 = (aq0 + 1) >> 2, ac1 = ((aq0 + 1) & 3) * 8;
    const int br0 = aq0 >> 4, bc0 = (aq0 & 15) * 8;
    const int br1 = (aq0 + 1) >> 4, bc1 = ((aq0 + 1) & 15) * 8;
    const bool ok0 = (col0 + bc0) < N;
    const bool ok1 = (col0 + bc1) < N;

    const int T = Kp >> 5;

    #define ISSUE(s, kt) do {                                                          \
        hf* As_ = AsBase + (s) * AS_ELEMS;                                             \
        hf* Bs_ = BsBase + (s) * BS_ELEMS;                                             \
        const int k0_ = (kt) * 32;                                                     \
        int kr0_ = k0_ + br0; if (kr0_ >= Khalf) kr0_ -= Khalf;                        \
        int kr1_ = k0_ + br1; if (kr1_ >= Khalf) kr1_ -= Khalf;                        \
        cpa16(&As_[ar0 * 40 + ac0], A + (size_t)(row0 + ar0) * Kp + k0_ + ac0, true);  \
        cpa16(&As_[ar1 * 40 + ac1], A + (size_t)(row0 + ar1) * Kp + k0_ + ac1, true);  \
        cpa16(&Bs_[br0 * 136 + bc0],                                                   \
              ok0 ? (Bm + (size_t)kr0_ * N + col0 + bc0) : Bm, ok0);                   \
        cpa16(&Bs_[br1 * 136 + bc1],                                                   \
              ok1 ? (Bm + (size_t)kr1_ * N + col0 + bc1) : Bm, ok1);                   \
    } while (0)

    #pragma unroll
    for (int s = 0; s < NSTAGE - 1; s++) {
        if (s < T) ISSUE(s, s);
        asm volatile("cp.async.commit_group;");
    }

    for (int kt = 0; kt < T; kt++) {
        asm volatile("cp.async.wait_group %0;" :: "n"(NSTAGE - 2));
        __syncthreads();

        const int cur = kt % NSTAGE;
        const hf* As = AsBase + cur * AS_ELEMS;
        const hf* Bs = BsBase + cur * BS_ELEMS;
        #pragma unroll
        for (int kk = 0; kk < 2; kk++) {
            unsigned af[4][4], bfg[4][2];
            #pragma unroll
            for (int i = 0; i < 4; i++) {
                const hf* p = &As[(wm * 64 + i * 16 + (lane & 15)) * 40 + kk * 16 + (lane >> 4) * 8];
                unsigned addr = (unsigned)__cvta_generic_to_shared(p);
                asm volatile("ldmatrix.sync.aligned.m8n8.x4.shared.b16 {%0,%1,%2,%3}, [%4];"
                             : "=r"(af[i][0]), "=r"(af[i][1]), "=r"(af[i][2]), "=r"(af[i][3])
                             : "r"(addr));
            }
            #pragma unroll
            for (int j = 0; j < 4; j++) {
                const hf* p = &Bs[(kk * 16 + (lane & 15)) * 136 + wn * 32 + j * 8];
                unsigned addr = (unsigned)__cvta_generic_to_shared(p);
                asm volatile("ldmatrix.sync.aligned.m8n8.x2.trans.shared.b16 {%0,%1}, [%2];"
                             : "=r"(bfg[j][0]), "=r"(bfg[j][1]) : "r"(addr));
            }
            #pragma unroll
            for (int i = 0; i < 4; i++)
                #pragma unroll
                for (int j = 0; j < 4; j++)
                    asm volatile(
                        "mma.sync.aligned.m16n8k16.row.col.f32.f16.f16.f32 "
                        "{%0,%1,%2,%3}, {%4,%5,%6,%7}, {%8,%9}, {%0,%1,%2,%3};"
                        : "+f"(acc[i][j][0]), "+f"(acc[i][j][1]), "+f"(acc[i][j][2]), "+f"(acc[i][j][3])
                        : "r"(af[i][0]), "r"(af[i][1]), "r"(af[i][2]), "r"(af[i][3]),
                          "r"(bfg[j][0]), "r"(bfg[j][1]));
        }

        if (kt + NSTAGE - 1 < T) ISSUE((kt + NSTAGE - 1) % NSTAGE, kt + NSTAGE - 1);
        asm volatile("cp.async.commit_group;");
    }
    #undef ISSUE

    // epilogue
    if (MODE == 4) {
        hf* C = (hf*)Cv;
        const int jblk = row0 >> 9;
        const int off  = (jblk == 0) ? o0 : (jblk == 1) ? o1 : (jblk == 2) ? o2 : o3;
        const int goff = (jblk == 0) ? 134 : (jblk == 1) ? 268 : (jblk == 2) ? 536 : 670;
        const int hmask = (1 << hdshift) - 1;
        const int Ktot = 2 * sec;
        #pragma unroll
        for (int i = 0; i < 4; i++)
            #pragma unroll
            for (int j = 0; j < 4; j++)
                #pragma unroll
                for (int g = 0; g < 4; g++) {
                    int rr = row0 + wm * 64 + i * 16 + (lane >> 2) + ((g >> 1) << 3);
                    int cc = col0 + wn * 32 + j * 8 + ((lane & 3) << 1) + (g & 1);
                    if (cc >= N) continue;
                    int n = rr & (NN - 1);
                    float v = acc[i][j][g];
                    if (splitN && cc >= splitN) {
                        int b = cc - splitN;
                        store2(C + (size_t)(n * BB + b) * Ktot, goff, sec, v);
                    } else {
                        int b = cc >> hdshift;
                        int c = cc & hmask;
                        store2(C + (size_t)(n * BB + b) * Ktot, off + c, sec, v);
                    }
                }
    } else {
        float* C = (float*)Cv;
        #pragma unroll
        for (int i = 0; i < 4; i++)
            #pragma unroll
            for (int j = 0; j < 4; j++)
                #pragma unroll
                for (int g = 0; g < 4; g++) {
                    int rr = row0 + wm * 64 + i * 16 + (lane >> 2) + ((g >> 1) << 3);
                    int cc = col0 + wn * 32 + j * 8 + ((lane & 3) << 1) + (g & 1);
                    if (cc >= N) continue;
                    float v = acc[i][j][g];
                    if (MODE == 2) {
                        v = 1.f / (1.f + expf(-(v + bias[cc])));
                        if (cc < splitN) C [(size_t)rr * splitN + cc]            = v;
                        else             C2[(size_t)rr * splitN + (cc - splitN)] = v;
                    } else { // MODE 3
                        C[(size_t)rr * ldC + cc] = tanhf(v + bias[cc]);
                    }
                }
    }
}

// ================= fp32 f32x2 SGEMM (setup GEMMs only) =====================
template<int MODE>   // MODE 0: plain, MODE 1: 2*acc - I
__global__ void __launch_bounds__(256)
sgemm(const float* __restrict__ A, const float* __restrict__ Bm, float* __restrict__ C,
      int M, int N, int K)
{
    __shared__ __align__(16) float As[2][16][132];
    __shared__ __align__(16) float Bsh[2][16][132];
    const int tid = threadIdx.x;
    const int tx  = tid & 15;
    const int ty  = tid >> 4;
    const int row0 = blockIdx.y * 128;
    const int col0 = blockIdx.x * 128;

    const int am  = tid >> 1;
    const int ak0 = (tid & 1) << 2;
    const int bk  = tid >> 5;
    const int bn  = (tid & 31) << 2;
    const int gn  = col0 + bn;
    const bool bok = gn < N;

    unsigned long long acc[8][4];
    #pragma unroll
    for (int i = 0; i < 8; i++)
        #pragma unroll
        for (int j = 0; j < 4; j++) acc[i][j] = 0ull;

    const int T = K >> 4;
    const float4 z4 = make_float4(0.f, 0.f, 0.f, 0.f);
    const float* Abase = A + (size_t)(row0 + am) * K + ak0;

    float4 ra0 = *(const float4*)(Abase);
    float4 ra1 = *(const float4*)(Abase + 8);
    float4 rb0 = bok ? *(const float4*)(Bm + (size_t)bk * N + gn) : z4;
    float4 rb1 = bok ? *(const float4*)(Bm + (size_t)(bk + 8) * N + gn) : z4;
    As[0][ak0 + 0][am] = ra0.x; As[0][ak0 + 1][am] = ra0.y;
    As[0][ak0 + 2][am] = ra0.z; As[0][ak0 + 3][am] = ra0.w;
    As[0][ak0 + 8][am] = ra1.x; As[0][ak0 + 9][am] = ra1.y;
    As[0][ak0 +10][am] = ra1.z; As[0][ak0 +11][am] = ra1.w;
    *(float4*)&Bsh[0][bk][bn]     = rb0;
    *(float4*)&Bsh[0][bk + 8][bn] = rb1;
    __syncthreads();

    for (int kt = 0; kt < T; kt++) {
        const int cur = kt & 1;
        if (kt + 1 < T) {
            const float* Ap = Abase + (kt + 1) * 16;
            ra0 = *(const float4*)(Ap);
            ra1 = *(const float4*)(Ap + 8);
            const int gk = (kt + 1) * 16;
            rb0 = bok ? *(const float4*)(Bm + (size_t)(gk + bk) * N + gn) : z4;
            rb1 = bok ? *(const float4*)(Bm + (size_t)(gk + bk + 8) * N + gn) : z4;
        }
        #pragma unroll
        for (int kk = 0; kk < 16; kk++) {
            float4 a0 = *(const float4*)&As[cur][kk][ty * 8];
            float4 a1 = *(const float4*)&As[cur][kk][ty * 8 + 4];
            ulonglong2 bp0 = *(const ulonglong2*)&Bsh[cur][kk][tx * 8];
            ulonglong2 bp1 = *(const ulonglong2*)&Bsh[cur][kk][tx * 8 + 4];
            unsigned long long b2[4] = { bp0.x, bp0.y, bp1.x, bp1.y };
            unsigned long long a2[8] = {
                bcast2(a0.x), bcast2(a0.y), bcast2(a0.z), bcast2(a0.w),
                bcast2(a1.x), bcast2(a1.y), bcast2(a1.z), bcast2(a1.w)
            };
            #pragma unroll
            for (int i = 0; i < 8; i++)
                #pragma unroll
                for (int j = 0; j < 4; j++)
                    fma2(acc[i][j], a2[i], b2[j]);
        }
        if (kt + 1 < T) {
            const int nxt = cur ^ 1;
            As[nxt][ak0 + 0][am] = ra0.x; As[nxt][ak0 + 1][am] = ra0.y;
            As[nxt][ak0 + 2][am] = ra0.z; As[nxt][ak0 + 3][am] = ra0.w;
            As[nxt][ak0 + 8][am] = ra1.x; As[nxt][ak0 + 9][am] = ra1.y;
            As[nxt][ak0 +10][am] = ra1.z; As[nxt][ak0 +11][am] = ra1.w;
            *(float4*)&Bsh[nxt][bk][bn]     = rb0;
            *(float4*)&Bsh[nxt][bk + 8][bn] = rb1;
        }
        __syncthreads();
    }

    #pragma unroll
    for (int i = 0; i < 8; i++) {
        const int rrow = row0 + ty * 8 + i;
        #pragma unroll
        for (int j = 0; j < 4; j++) {
            #pragma unroll
            for (int h = 0; h < 2; h++) {
                const int cc = col0 + tx * 8 + 2 * j + h;
                if (cc >= N) continue;
                float v = h ? __uint_as_float((unsigned)(acc[i][j] >> 32))
                            : __uint_as_float((unsigned)(acc[i][j]));
                if (MODE == 0) C[(size_t)rrow * N + cc] = v;
                else           C[(size_t)rrow * N + cc] = 2.f * v - ((rrow == cc) ? 1.f : 0.f);
            }
        }
    }
}

// ---------------- small kernels ----------------
__global__ void k_zero(float* p, int n) {
    int i = blockIdx.x * blockDim.x + threadIdx.x;
    if (i < n) p[i] = 0.f;
}

__global__ void k_splitA(const float* __restrict__ in, hf* __restrict__ out, int K, int total) {
    int i = blockIdx.x * blockDim.x + threadIdx.x;
    if (i >= total) return;
    int m = i / K, k = i - m * K;
    hf h, l; split2h(in[i], h, l);
    hf* p = out + (size_t)m * 2 * K;
    p[k] = h; p[K + k] = l;
}

__global__ void k_packB(const float* __restrict__ in, hf* __restrict__ out, int total) {
    int i = blockIdx.x * blockDim.x + threadIdx.x;
    if (i < total) out[i] = __float2half(in[i]);
}

__global__ void k_packB_dec(const float* __restrict__ in, hf* __restrict__ out) {
    int i = blockIdx.x * blockDim.x + threadIdx.x;
    if (i >= ROWS * DDEC) return;
    int row = i >> 7, c = i & 127;
    int n = row >> 6, b = row & 63;
    out[(size_t)n * NHBD + b * DDEC + c] = __float2half(in[i]);
}
__global__ void k_zero_go(hf* __restrict__ hB) {
    int i = blockIdx.x * blockDim.x + threadIdx.x;
    if (i >= NN * BB) return;
    int n = i >> 6, b = i & 63;
    hB[(size_t)n * NHBD + BB * DDEC + b] = __float2half(0.f);
}

__global__ void k_eW(const float* __restrict__ We, const float* __restrict__ Mem,
                     float* __restrict__ e) {
    int idx = blockIdx.x * blockDim.x + threadIdx.x;
    if (idx >= NN * 64) return;
    int n = idx >> 6, d = idx & 63;
    float s = 0.f;
    #pragma unroll
    for (int k = 0; k < 20; k++) s += We[n * 20 + k] * Mem[k * 64 + d];
    e[idx] = s;
}

__global__ void k_gsoftmax(const float* __restrict__ ea, const float* __restrict__ eb,
                           float* __restrict__ g) {
    __shared__ float er[64];
    __shared__ float buf[NN];
    __shared__ float red[128];
    int n = blockIdx.x, tid = threadIdx.x;
    if (tid < 64) er[tid] = ea[n * 64 + tid];
    __syncthreads();
    for (int m = tid; m < NN; m += 128) {
        float s = 0.f;
        #pragma unroll
        for (int d = 0; d < 64; d++) s += er[d] * eb[m * 64 + d];
        buf[m] = s > 0.f ? s : 0.f;
    }
    __syncthreads();
    float mx = -1e30f;
    for (int m = tid; m < NN; m += 128) mx = fmaxf(mx, buf[m]);
    red[tid] = mx; __syncthreads();
    for (int s = 64; s > 0; s >>= 1) { if (tid < s) red[tid] = fmaxf(red[tid], red[tid + s]); __syncthreads(); }
    mx = red[0]; __syncthreads();
    float sm = 0.f;
    for (int m = tid; m < NN; m += 128) { float e = expf(buf[m] - mx); buf[m] = e; sm += e; }
    red[tid] = sm; __syncthreads();
    for (int s = 64; s > 0; s >>= 1) { if (tid < s) red[tid] += red[tid + s]; __syncthreads(); }
    float inv = 1.f / red[0];
    for (int m = tid; m < NN; m += 128) g[n * NN + m] = buf[m] * inv;
}

__global__ void k_xT(const float* __restrict__ x, float* __restrict__ xT) {
    int idx = blockIdx.x * blockDim.x + threadIdx.x;
    if (idx >= BB * NN * LL) return;
    int l = idx % LL;
    int n = (idx / LL) % NN;
    int b = idx / (LL * NN);
    xT[(n * LL + l) * BB + b] = x[idx];
}

__global__ void k_fill_enc_x(hf* __restrict__ xg, const float* __restrict__ xT,
                             const float* __restrict__ GX, int l) {
    int row = blockIdx.x * blockDim.x + threadIdx.x;
    if (row >= ROWS) return;
    int n = row >> 6, b = row & 63;
    hf* p = xg + (size_t)row * KPE;
    float xv = xT[(n * LL + l) * BB + b];
    store2(p, 0, SECE, xv);
    store2(p, 195, SECE, xv);
    store2(p, 65,  SECE, GX[(size_t)(0 * NN + n) * (LL * BB) + l * BB + b]);
    store2(p, 130, SECE, GX[(size_t)(1 * NN + n) * (LL * BB) + l * BB + b]);
    store2(p, 260, SECE, GX[(size_t)(2 * NN + n) * (LL * BB) + l * BB + b]);
    store2(p, 325, SECE, GX[(size_t)(3 * NN + n) * (LL * BB) + l * BB + b]);
}

__global__ void k_fill_h_id(hf* __restrict__ xg, const float* __restrict__ h,
                            int hdshift, int sec, int off0, int off3, int total) {
    int i = blockIdx.x * blockDim.x + threadIdx.x;
    if (i >= total) return;
    int row = i >> hdshift;
    int c   = i & ((1 << hdshift) - 1);
    float v = h[i];
    hf* p = xg + (size_t)row * 2 * sec;
    store2(p, off0 + c, sec, v);
    store2(p, off3 + c, sec, v);
}

// FUSED (2/thread): zh = z*h -> xg id-blocks + hB (half2, width Ncols)
__global__ void k_zh_pack(const float* __restrict__ z, const float* __restrict__ h,
                          hf* __restrict__ xg, hf* __restrict__ hB,
                          int hdshift, int sec, int off0, int off3, int Ncols, int total2) {
    int i = blockIdx.x * blockDim.x + threadIdx.x;
    if (i >= total2) return;
    int base = i * 2;
    int row = base >> hdshift;
    int c   = base & ((1 << hdshift) - 1);
    float2 zv = *(const float2*)(z + base);
    float2 hv = *(const float2*)(h + base);
    float v0 = zv.x * hv.x, v1 = zv.y * hv.y;
    hf* p = xg + (size_t)row * 2 * sec;
    store2(p, off0 + c, sec, v0);     store2(p, off0 + c + 1, sec, v1);
    store2(p, off3 + c, sec, v0);     store2(p, off3 + c + 1, sec, v1);
    int n = row >> 6, b = row & 63;
    __half2 hv2 = __floats2half2_rn(v0, v1);
    *(__half2*)(hB + (size_t)n * Ncols + ((size_t)b << hdshift) + c) = hv2;
}

// FUSED (2/thread): h' = r*h+(1-r)*hc -> h, xg id-blocks, hB (encoder)
__global__ void k_hupd_pack(const float* __restrict__ r, const float* __restrict__ hc,
                            float* __restrict__ h,
                            hf* __restrict__ xg, hf* __restrict__ hB,
                            int hdshift, int sec, int off0, int off3, int Ncols, int total2) {
    int i = blockIdx.x * blockDim.x + threadIdx.x;
    if (i >= total2) return;
    int base = i * 2;
    int row = base >> hdshift;
    int c   = base & ((1 << hdshift) - 1);
    float2 rv = *(const float2*)(r + base);
    float2 hcv = *(const float2*)(hc + base);
    float2 hv = *(const float2*)(h + base);
    float hn0 = rv.x * hv.x + (1.f - rv.x) * hcv.x;
    float hn1 = rv.y * hv.y + (1.f - rv.y) * hcv.y;
    *(float2*)(h + base) = make_float2(hn0, hn1);
    hf* p = xg + (size_t)row * 2 * sec;
    store2(p, off0 + c, sec, hn0);    store2(p, off0 + c + 1, sec, hn1);
    store2(p, off3 + c, sec, hn0);    store2(p, off3 + c + 1, sec, hn1);
    int n = row >> 6, b = row & 63;
    __half2 hv2 = __floats2half2_rn(hn0, hn1);
    *(__half2*)(hB + (size_t)n * Ncols + ((size_t)b << hdshift) + c) = hv2;
}

// fill decoder go-id + ycov channels for step t (used once, t=0)
__global__ void k_fill_dec(hf* __restrict__ xg, const float* __restrict__ go,
                           const float* __restrict__ tt, int t) {
    int row = blockIdx.x * blockDim.x + threadIdx.x;
    if (row >= ROWS) return;
    int b = row & 63;
    hf* p = xg + (size_t)row * KPD;
    float gv = go[row];
    store2(p, 0,   SECD, gv);
    store2(p, 402, SECD, gv);
    #pragma unroll
    for (int c = 0; c < 5; c++) {
        float v = tt[(b * 5 + c) * HH + t];
        store2(p, 1 + c,   SECD, v); store2(p, 135 + c, SECD, v);
        store2(p, 269 + c, SECD, v); store2(p, 403 + c, SECD, v);
        store2(p, 537 + c, SECD, v); store2(p, 671 + c, SECD, v);
    }
}

__global__ void k_attn(const float* __restrict__ h, const float* __restrict__ Wq,
                       const float* __restrict__ Mem, float* __restrict__ hde) {
    __shared__ float hr[64];
    __shared__ float q[64];
    __shared__ float sc[20];
    int row = blockIdx.x, tid = threadIdx.x;
    hr[tid] = h[row * 64 + tid];
    __syncthreads();
    float s = 0.f;
    #pragma unroll
    for (int c = 0; c < 64; c++) s += hr[c] * Wq[c * 64 + tid];
    q[tid] = s;
    __syncthreads();
    if (tid < 20) {
        float v = 0.f;
        #pragma unroll
        for (int c = 0; c < 64; c++) v += q[c] * Mem[tid * 64 + c];
        sc[tid] = v;
    }
    __syncthreads();
    if (tid == 0) {
        float mx = -1e30f;
        for (int j = 0; j < 20; j++) mx = fmaxf(mx, sc[j]);
        float sm = 0.f;
        for (int j = 0; j < 20; j++) { sc[j] = expf(sc[j] - mx); sm += sc[j]; }
        float inv = 1.f / sm;
        for (int j = 0; j < 20; j++) sc[j] *= inv;
    }
    __syncthreads();
    float ha = 0.f;
    #pragma unroll
    for (int j = 0; j < 20; j++) ha += sc[j] * Mem[j * 64 + tid];
    hde[row * 128 + tid]      = hr[tid];
    hde[row * 128 + 64 + tid] = ha;
}

// FUSED decoder h update + pack + projection + go write + NEXT-step fill
// 64 thr/row, 2 c/thread. After the reduction, all threads see red[0]:
//   tid 0 writes go-id channels for step t+1; tids <30 write ycov(t+1) channels.
__global__ void k_hupd_dec_pack(const float* __restrict__ r, const float* __restrict__ hc,
                                float* __restrict__ h, const float* __restrict__ pW,
                                const float* __restrict__ pb, float* __restrict__ go,
                                float* __restrict__ out, int t,
                                hf* __restrict__ xg, hf* __restrict__ hB,
                                const float* __restrict__ tt) {
    __shared__ float red[64];
    int row = blockIdx.x, tid = threadIdx.x;
    int c = tid * 2;
    int i = row * 128 + c;
    float2 rv = *(const float2*)(r + i);
    float2 hcv = *(const float2*)(hc + i);
    float2 hv = *(const float2*)(h + i);
    float hn0 = rv.x * hv.x + (1.f - rv.x) * hcv.x;
    float hn1 = rv.y * hv.y + (1.f - rv.y) * hcv.y;
    *(float2*)(h + i) = make_float2(hn0, hn1);
    hf* p = xg + (size_t)row * KPD;
    store2(p, 6 + c, SECD, hn0);   store2(p, 6 + c + 1, SECD, hn1);
    store2(p, 408 + c, SECD, hn0); store2(p, 408 + c + 1, SECD, hn1);
    int n = row >> 6, b = row & 63;
    __half2 hv2 = __floats2half2_rn(hn0, hn1);
    *(__half2*)(hB + (size_t)n * NHBD + b * DDEC + c) = hv2;
    float2 pw = *(const float2*)(pW + c);
    red[tid] = hn0 * pw.x + hn1 * pw.y;
    __syncthreads();
    for (int s = 32; s > 0; s >>= 1) { if (tid < s) red[tid] += red[tid + s]; __syncthreads(); }
    float g = red[0] + pb[0];
    if (tid == 0) {
        go[row] = g;
        out[(b * NN + n) * HH + t] = g;
        hB[(size_t)n * NHBD + BB * DDEC + b] = __float2half(g);   // go column for next conv
        if (t + 1 < HH) {
            store2(p, 0,   SECD, g);
            store2(p, 402, SECD, g);
        }
    }
    // next-step ycov fill (constant across the step; needs no g)
    if (t + 1 < HH && tid < 30) {
        const int offs0[6] = {1, 135, 269, 403, 537, 671};
        int pos = tid / 5, ch = tid - pos * 5;
        float v = tt[(b * 5 + ch) * HH + (t + 1)];
        store2(p, offs0[pos] + ch, SECD, v);
    }
}

// ---------------- host side ----------------
static void bgemm_launch(int mode, const hf* A, const hf* B, void* C,
                         int M, int N, int Kp,
                         const float* bias = nullptr, float* C2 = nullptr,
                         int splitN = 0, int ldC = 0, int hdshift = 0, int sec = 0,
                         int o0 = 0, int o1 = 0, int o2 = 0, int o3 = 0)
{
    dim3 grid((N + 127) / 128, M / 128);
    switch (mode) {
        case 2: bgemm<2><<<grid, 256, SMEM_BYTES>>>(A, B, C, M, N, Kp, bias, C2, splitN, ldC, hdshift, sec, o0, o1, o2, o3); break;
        case 3: bgemm<3><<<grid, 256, SMEM_BYTES>>>(A, B, C, M, N, Kp, bias, C2, splitN, ldC, hdshift, sec, o0, o1, o2, o3); break;
        case 4: bgemm<4><<<grid, 256, SMEM_BYTES>>>(A, B, C, M, N, Kp, bias, C2, splitN, ldC, hdshift, sec, o0, o1, o2, o3); break;
    }
}

extern "C" void kernel_launch(void* const* d_in, const int* in_sizes, int n_in,
                              void* d_out, int out_size)
{
    const float* x   = (const float*)d_in[0];
    const float* tt  = (const float*)d_in[3];
    const float* Mem = (const float*)d_in[5];
    const float* Wq  = (const float*)d_in[6];
    const float* We1 = (const float*)d_in[7];
    const float* We2 = (const float*)d_in[8];
    const float* egW = (const float*)d_in[9];
    const float* egb = (const float*)d_in[10];
    const float* euW = (const float*)d_in[11];
    const float* eub = (const float*)d_in[12];
    const float* dgW = (const float*)d_in[13];
    const float* dgb = (const float*)d_in[14];
    const float* duW = (const float*)d_in[15];
    const float* dub = (const float*)d_in[16];
    const float* pW  = (const float*)d_in[17];
    const float* pb  = (const float*)d_in[18];
    float* out = (float*)d_out;

    cudaFuncSetAttribute(bgemm<2>, cudaFuncAttributeMaxDynamicSharedMemorySize, SMEM_BYTES);
    cudaFuncSetAttribute(bgemm<3>, cudaFuncAttributeMaxDynamicSharedMemorySize, SMEM_BYTES);
    cudaFuncSetAttribute(bgemm<4>, cudaFuncAttributeMaxDynamicSharedMemorySize, SMEM_BYTES);

    float *S, *e1, *e2, *xT, *GX, *henc, *hdec, *z, *r, *hc, *go;
    hf *Sbig, *hB, *xgE, *xgD, *egWB, *euWB, *dgWB, *duWB;
    cudaGetSymbolAddress((void**)&S,    g_S);
    cudaGetSymbolAddress((void**)&e1,   g_e1);
    cudaGetSymbolAddress((void**)&e2,   g_e2);
    cudaGetSymbolAddress((void**)&xT,   g_xT);
    cudaGetSymbolAddress((void**)&GX,   g_GX);
    cudaGetSymbolAddress((void**)&henc, g_henc);
    cudaGetSymbolAddress((void**)&hdec, g_hdec);
    cudaGetSymbolAddress((void**)&z,    g_z);
    cudaGetSymbolAddress((void**)&r,    g_r);
    cudaGetSymbolAddress((void**)&hc,   g_hc);
    cudaGetSymbolAddress((void**)&go,   g_go);
    cudaGetSymbolAddress((void**)&Sbig, g_Sbig);
    cudaGetSymbolAddress((void**)&hB,   g_hB);
    cudaGetSymbolAddress((void**)&xgE,  g_xgE);
    cudaGetSymbolAddress((void**)&xgD,  g_xgD);
    cudaGetSymbolAddress((void**)&egWB, g_egWB);
    cudaGetSymbolAddress((void**)&euWB, g_euWB);
    cudaGetSymbolAddress((void**)&dgWB, g_dgWB);
    cudaGetSymbolAddress((void**)&duWB, g_duWB);

    // --- weight packs ---
    k_packB<<<(KENC * 128 + 255) / 256, 256>>>(egW, egWB, KENC * 128);
    k_packB<<<(KENC * 64  + 255) / 256, 256>>>(euW, euWB, KENC * 64);
    k_packB<<<(KDEC * 256 + 255) / 256, 256>>>(dgW, dgWB, KDEC * 256);
    k_packB<<<(KDEC * 128 + 255) / 256, 256>>>(duW, duWB, KDEC * 128);

    // --- supports (fp32) ---
    k_eW<<<(NN * 64 + 255) / 256, 256>>>(We1, Mem, e1);
    k_eW<<<(NN * 64 + 255) / 256, 256>>>(We2, Mem, e2);
    k_gsoftmax<<<NN, 128>>>(e1, e2, S);
    k_gsoftmax<<<NN, 128>>>(e2, e1, S + 2 * NN * NN);
    {
        dim3 g1(NN / 128, NN / 128);
        sgemm<1><<<g1, 256>>>(S,               S,               S + 1 * NN * NN, NN, NN, NN);
        sgemm<1><<<g1, 256>>>(S + 2 * NN * NN, S + 2 * NN * NN, S + 3 * NN * NN, NN, NN, NN);
    }
    k_splitA<<<(4 * NN * NN + 255) / 256, 256>>>(S, Sbig, NN, 4 * NN * NN);

    // --- encoder x precompute (fp32) ---
    k_xT<<<(BB * NN * LL + 255) / 256, 256>>>(x, xT);
    {
        dim3 g2((LL * BB + 127) / 128, 4 * NN / 128);
        sgemm<0><<<g2, 256>>>(S, xT, GX, 4 * NN, LL * BB, NN);
    }

    // --- init states ---
    k_zero<<<(ROWS * RNN + 255) / 256, 256>>>(henc, ROWS * RNN);
    k_zero<<<(ROWS + 255) / 256, 256>>>(go, ROWS);
    k_fill_h_id<<<(ROWS * RNN) / 256, 256>>>(xgE, henc, 6, SECE, 1, 196, ROWS * RNN);
    k_packB<<<(ROWS * RNN + 255) / 256, 256>>>(henc, hB, ROWS * RNN);

    // --- encoder ---
    for (int l = 0; l < LL; l++) {
        k_fill_enc_x<<<ROWS / 256, 256>>>(xgE, xT, GX, l);
        bgemm_launch(4, Sbig, hB, xgE, 4 * NN, BB * RNN, KGC,
                     nullptr, nullptr, 0, 0, 6, SECE, 66, 131, 261, 326);
        bgemm_launch(2, xgE, egWB, z, ROWS, 2 * RNN, KPE, egb, r, RNN);
        k_zh_pack<<<(ROWS * RNN / 2) / 256, 256>>>(z, henc, xgE, hB, 6, SECE, 1, 196, BB * RNN, ROWS * RNN / 2);
        bgemm_launch(4, Sbig, hB, xgE, 4 * NN, BB * RNN, KGC,
                     nullptr, nullptr, 0, 0, 6, SECE, 66, 131, 261, 326);
        bgemm_launch(3, xgE, euWB, hc, ROWS, RNN, KPE, eub, nullptr, 0, RNN);
        k_hupd_pack<<<(ROWS * RNN / 2) / 256, 256>>>(r, hc, henc, xgE, hB, 6, SECE, 1, 196, BB * RNN, ROWS * RNN / 2);
    }

    // --- memory attention -> decoder initial hidden ---
    k_attn<<<ROWS, 64>>>(henc, Wq, Mem, hdec);
    k_fill_h_id<<<(ROWS * DDEC) / 256, 256>>>(xgD, hdec, 7, SECD, 6, 408, ROWS * DDEC);
    k_packB_dec<<<(ROWS * DDEC + 255) / 256, 256>>>(hdec, hB);
    k_zero_go<<<(NN * BB + 255) / 256, 256>>>(hB);
    k_fill_dec<<<ROWS / 256, 256>>>(xgD, go, tt, 0);   // step-0 fill (later steps fused)

    // --- decoder ---
    for (int t = 0; t < HH; t++) {
        // conv(h) + conv(go) fused (go cols at splitN = BB*DDEC)
        bgemm_launch(4, Sbig, hB, xgD, 4 * NN, NHBD, KGC,
                     nullptr, nullptr, BB * DDEC, 0, 7, SECD, 140, 274, 542, 676);
        bgemm_launch(2, xgD, dgWB, z, ROWS, 2 * DDEC, KPD, dgb, r, DDEC);
        k_zh_pack<<<(ROWS * DDEC / 2) / 256, 256>>>(z, hdec, xgD, hB, 7, SECD, 6, 408, NHBD, ROWS * DDEC / 2);
        bgemm_launch(4, Sbig, hB, xgD, 4 * NN, NHBD, KGC,
                     nullptr, nullptr, BB * DDEC, 0, 7, SECD, 140, 274, 542, 676);
        bgemm_launch(3, xgD, duWB, hc, ROWS, DDEC, KPD, dub, nullptr, 0, DDEC);
        k_hupd_dec_pack<<<ROWS, 64>>>(r, hc, hdec, pW, pb, go, out, t, xgD, hB, tt);
    }
}

// round 17
// speedup vs baseline: 1.0434x; 1.0030x over previous
#include <cuda_runtime.h>
#include <cuda_fp16.h>
#include <math.h>

// ---------------- problem constants ----------------
#define NN   512
#define BB   64
#define LL   12
#define HH   12
#define RNN  64
#define DDEC 128
#define KENC 390
#define KDEC 804
#define SECE 416
#define SECD 832
#define KPE  (2*SECE)   // 832
#define KPD  (2*SECD)   // 1664
#define KGC  (2*NN)     // 1024
#define ROWS (NN*BB)    // 32768
#define NHBD (BB*DDEC+64) // 8256: dec hB width (h cols + 64 go cols)

// bgemm pipeline: 4 stages of As(128x40 hf) + Bs(32x136 hf) -> 75776 B, 2 CTA/SM
#define AS_ELEMS (128*40)
#define BS_ELEMS (32*136)
#define NSTAGE   4
#define SMEM_BYTES (NSTAGE * (AS_ELEMS + BS_ELEMS) * 2)   // 75776

typedef __half hf;

// ---------------- scratch (device globals; zero-init, no allocation) ----------------
__device__ float g_S[4*NN*NN];
__device__ float g_e1[NN*64];
__device__ float g_e2[NN*64];
__device__ float g_xT[NN*LL*BB];
__device__ float g_GX[4*NN*LL*BB];
__device__ float g_henc[ROWS*RNN];
__device__ float g_hdec[ROWS*DDEC];
__device__ float g_z [ROWS*DDEC];
__device__ float g_r [ROWS*DDEC];
__device__ float g_hc[ROWS*DDEC];
__device__ float g_go[ROWS];
// fp16 2-term split operands. B stored ONCE (K rows); bgemm wraps k>=Kp/2.
__device__ hf g_Sbig [4*NN*KGC];       // A: [hi|lo], 2048 x 1024
__device__ hf g_hB   [NN*NHBD];        // B: hi only, 512 x 8256 max
__device__ hf g_xgE  [ROWS*KPE];
__device__ hf g_xgD  [ROWS*KPD];
__device__ hf g_egWB [SECE*128];
__device__ hf g_euWB [SECE*64];
__device__ hf g_dgWB [SECD*256];
__device__ hf g_duWB [SECD*128];

// ---------------- helpers ----------------
__device__ __forceinline__ void split2h(float v, hf &h, hf &l) {
    h = __float2half(v);
    l = __float2half(v - __half2float(h));
}
__device__ __forceinline__ void store2(hf* p, int off, int sec, float v) {
    hf h, l; split2h(v, h, l);
    p[off] = h; p[sec + off] = l;
}
__device__ __forceinline__ void fma2(unsigned long long &d, unsigned long long a, unsigned long long b) {
    asm("fma.rn.f32x2 %0, %1, %2, %0;" : "+l"(d) : "l"(a), "l"(b));
}
__device__ __forceinline__ unsigned long long bcast2(float x) {
    unsigned long long r;
    asm("mov.b64 %0, {%1, %1};" : "=l"(r) : "f"(x));
    return r;
}
__device__ __forceinline__ void cpa16(void* s, const void* g, bool ok) {
    unsigned sa = (unsigned)__cvta_generic_to_shared(s);
    int sz = ok ? 16 : 0;
    asm volatile("cp.async.cg.shared.global [%0], [%1], 16, %2;"
                 :: "r"(sa), "l"(g), "r"(sz));
}

// ================= fp16 tensor-core GEMM, 128x128x32, 4-stage cp.async ==========
// Single __syncthreads per K-tile (R10/R14-proven). B stored once, row wraps.
// MODE 2: v=sigmoid(acc+bias[c]); c<splitN -> Cz else Cr
// MODE 3: C[r*ldC+c] = tanh(acc+bias[c])
// MODE 4: conv scatter into xg pairs. splitN = go-column boundary (0 = none).
template<int MODE>
__global__ void __launch_bounds__(256)
bgemm(const hf* __restrict__ A, const hf* __restrict__ Bm, void* __restrict__ Cv,
      int M, int N, int Kp, const float* __restrict__ bias, float* __restrict__ C2,
      int splitN, int ldC, int hdshift, int sec, int o0, int o1, int o2, int o3)
{
    extern __shared__ __align__(16) char smem_raw[];
    hf* AsBase = (hf*)smem_raw;
    hf* BsBase = (hf*)smem_raw + NSTAGE * AS_ELEMS;

    const int tid  = threadIdx.x;
    const int lane = tid & 31;
    const int warp = tid >> 5;
    const int wm   = warp & 1;
    const int wn   = warp >> 1;
    const int row0 = blockIdx.y * 128;
    const int col0 = blockIdx.x * 128;
    const int Khalf = Kp >> 1;

    float acc[4][4][4];
    #pragma unroll
    for (int i = 0; i < 4; i++)
        #pragma unroll
        for (int j = 0; j < 4; j++)
            #pragma unroll
            for (int g = 0; g < 4; g++) acc[i][j][g] = 0.f;

    const int aq0 = tid * 2;
    const int ar0 = aq0 >> 2, ac0 = (aq0 & 3) * 8;
    const int ar1 = (aq0 + 1) >> 2, ac1 = ((aq0 + 1) & 3) * 8;
    const int br0 = aq0 >> 4, bc0 = (aq0 & 15) * 8;
    const int br1 = (aq0 + 1) >> 4, bc1 = ((aq0 + 1) & 15) * 8;
    const bool ok0 = (col0 + bc0) < N;
    const bool ok1 = (col0 + bc1) < N;

    const int T = Kp >> 5;

    #define ISSUE(s, kt) do {                                                          \
        hf* As_ = AsBase + (s) * AS_ELEMS;                                             \
        hf* Bs_ = BsBase + (s) * BS_ELEMS;                                             \
        const int k0_ = (kt) * 32;                                                     \
        int kr0_ = k0_ + br0; if (kr0_ >= Khalf) kr0_ -= Khalf;                        \
        int kr1_ = k0_ + br1; if (kr1_ >= Khalf) kr1_ -= Khalf;                        \
        cpa16(&As_[ar0 * 40 + ac0], A + (size_t)(row0 + ar0) * Kp + k0_ + ac0, true);  \
        cpa16(&As_[ar1 * 40 + ac1], A + (size_t)(row0 + ar1) * Kp + k0_ + ac1, true);  \
        cpa16(&Bs_[br0 * 136 + bc0],                                                   \
              ok0 ? (Bm + (size_t)kr0_ * N + col0 + bc0) : Bm, ok0);                   \
        cpa16(&Bs_[br1 * 136 + bc1],                                                   \
              ok1 ? (Bm + (size_t)kr1_ * N + col0 + bc1) : Bm, ok1);                   \
    } while (0)

    #pragma unroll
    for (int s = 0; s < NSTAGE - 1; s++) {
        if (s < T) ISSUE(s, s);
        asm volatile("cp.async.commit_group;");
    }

    for (int kt = 0; kt < T; kt++) {
        asm volatile("cp.async.wait_group %0;" :: "n"(NSTAGE - 2));
        __syncthreads();

        const int cur = kt % NSTAGE;
        const hf* As = AsBase + cur * AS_ELEMS;
        const hf* Bs = BsBase + cur * BS_ELEMS;
        #pragma unroll
        for (int kk = 0; kk < 2; kk++) {
            unsigned af[4][4], bfg[4][2];
            #pragma unroll
            for (int i = 0; i < 4; i++) {
                const hf* p = &As[(wm * 64 + i * 16 + (lane & 15)) * 40 + kk * 16 + (lane >> 4) * 8];
                unsigned addr = (unsigned)__cvta_generic_to_shared(p);
                asm volatile("ldmatrix.sync.aligned.m8n8.x4.shared.b16 {%0,%1,%2,%3}, [%4];"
                             : "=r"(af[i][0]), "=r"(af[i][1]), "=r"(af[i][2]), "=r"(af[i][3])
                             : "r"(addr));
            }
            #pragma unroll
            for (int j = 0; j < 4; j++) {
                const hf* p = &Bs[(kk * 16 + (lane & 15)) * 136 + wn * 32 + j * 8];
                unsigned addr = (unsigned)__cvta_generic_to_shared(p);
                asm volatile("ldmatrix.sync.aligned.m8n8.x2.trans.shared.b16 {%0,%1}, [%2];"
                             : "=r"(bfg[j][0]), "=r"(bfg[j][1]) : "r"(addr));
            }
            #pragma unroll
            for (int i = 0; i < 4; i++)
                #pragma unroll
                for (int j = 0; j < 4; j++)
                    asm volatile(
                        "mma.sync.aligned.m16n8k16.row.col.f32.f16.f16.f32 "
                        "{%0,%1,%2,%3}, {%4,%5,%6,%7}, {%8,%9}, {%0,%1,%2,%3};"
                        : "+f"(acc[i][j][0]), "+f"(acc[i][j][1]), "+f"(acc[i][j][2]), "+f"(acc[i][j][3])
                        : "r"(af[i][0]), "r"(af[i][1]), "r"(af[i][2]), "r"(af[i][3]),
                          "r"(bfg[j][0]), "r"(bfg[j][1]));
        }

        if (kt + NSTAGE - 1 < T) ISSUE((kt + NSTAGE - 1) % NSTAGE, kt + NSTAGE - 1);
        asm volatile("cp.async.commit_group;");
    }
    #undef ISSUE

    // epilogue
    if (MODE == 4) {
        hf* C = (hf*)Cv;
        const int jblk = row0 >> 9;
        const int off  = (jblk == 0) ? o0 : (jblk == 1) ? o1 : (jblk == 2) ? o2 : o3;
        const int goff = (jblk == 0) ? 134 : (jblk == 1) ? 268 : (jblk == 2) ? 536 : 670;
        const int hmask = (1 << hdshift) - 1;
        const int Ktot = 2 * sec;
        #pragma unroll
        for (int i = 0; i < 4; i++)
            #pragma unroll
            for (int j = 0; j < 4; j++)
                #pragma unroll
                for (int g = 0; g < 4; g++) {
                    int rr = row0 + wm * 64 + i * 16 + (lane >> 2) + ((g >> 1) << 3);
                    int cc = col0 + wn * 32 + j * 8 + ((lane & 3) << 1) + (g & 1);
                    if (cc >= N) continue;
                    int n = rr & (NN - 1);
                    float v = acc[i][j][g];
                    if (splitN && cc >= splitN) {
                        int b = cc - splitN;
                        store2(C + (size_t)(n * BB + b) * Ktot, goff, sec, v);
                    } else {
                        int b = cc >> hdshift;
                        int c = cc & hmask;
                        store2(C + (size_t)(n * BB + b) * Ktot, off + c, sec, v);
                    }
                }
    } else {
        float* C = (float*)Cv;
        #pragma unroll
        for (int i = 0; i < 4; i++)
            #pragma unroll
            for (int j = 0; j < 4; j++)
                #pragma unroll
                for (int g = 0; g < 4; g++) {
                    int rr = row0 + wm * 64 + i * 16 + (lane >> 2) + ((g >> 1) << 3);
                    int cc = col0 + wn * 32 + j * 8 + ((lane & 3) << 1) + (g & 1);
                    if (cc >= N) continue;
                    float v = acc[i][j][g];
                    if (MODE == 2) {
                        v = 1.f / (1.f + expf(-(v + bias[cc])));
                        if (cc < splitN) C [(size_t)rr * splitN + cc]            = v;
                        else             C2[(size_t)rr * splitN + (cc - splitN)] = v;
                    } else { // MODE 3
                        C[(size_t)rr * ldC + cc] = tanhf(v + bias[cc]);
                    }
                }
    }
}

// ================= fp32 f32x2 SGEMM (setup GEMMs only) =====================
template<int MODE>   // MODE 0: plain, MODE 1: 2*acc - I
__global__ void __launch_bounds__(256)
sgemm(const float* __restrict__ A, const float* __restrict__ Bm, float* __restrict__ C,
      int M, int N, int K)
{
    __shared__ __align__(16) float As[2][16][132];
    __shared__ __align__(16) float Bsh[2][16][132];
    const int tid = threadIdx.x;
    const int tx  = tid & 15;
    const int ty  = tid >> 4;
    const int row0 = blockIdx.y * 128;
    const int col0 = blockIdx.x * 128;

    const int am  = tid >> 1;
    const int ak0 = (tid & 1) << 2;
    const int bk  = tid >> 5;
    const int bn  = (tid & 31) << 2;
    const int gn  = col0 + bn;
    const bool bok = gn < N;

    unsigned long long acc[8][4];
    #pragma unroll
    for (int i = 0; i < 8; i++)
        #pragma unroll
        for (int j = 0; j < 4; j++) acc[i][j] = 0ull;

    const int T = K >> 4;
    const float4 z4 = make_float4(0.f, 0.f, 0.f, 0.f);
    const float* Abase = A + (size_t)(row0 + am) * K + ak0;

    float4 ra0 = *(const float4*)(Abase);
    float4 ra1 = *(const float4*)(Abase + 8);
    float4 rb0 = bok ? *(const float4*)(Bm + (size_t)bk * N + gn) : z4;
    float4 rb1 = bok ? *(const float4*)(Bm + (size_t)(bk + 8) * N + gn) : z4;
    As[0][ak0 + 0][am] = ra0.x; As[0][ak0 + 1][am] = ra0.y;
    As[0][ak0 + 2][am] = ra0.z; As[0][ak0 + 3][am] = ra0.w;
    As[0][ak0 + 8][am] = ra1.x; As[0][ak0 + 9][am] = ra1.y;
    As[0][ak0 +10][am] = ra1.z; As[0][ak0 +11][am] = ra1.w;
    *(float4*)&Bsh[0][bk][bn]     = rb0;
    *(float4*)&Bsh[0][bk + 8][bn] = rb1;
    __syncthreads();

    for (int kt = 0; kt < T; kt++) {
        const int cur = kt & 1;
        if (kt + 1 < T) {
            const float* Ap = Abase + (kt + 1) * 16;
            ra0 = *(const float4*)(Ap);
            ra1 = *(const float4*)(Ap + 8);
            const int gk = (kt + 1) * 16;
            rb0 = bok ? *(const float4*)(Bm + (size_t)(gk + bk) * N + gn) : z4;
            rb1 = bok ? *(const float4*)(Bm + (size_t)(gk + bk + 8) * N + gn) : z4;
        }
        #pragma unroll
        for (int kk = 0; kk < 16; kk++) {
            float4 a0 = *(const float4*)&As[cur][kk][ty * 8];
            float4 a1 = *(const float4*)&As[cur][kk][ty * 8 + 4];
            ulonglong2 bp0 = *(const ulonglong2*)&Bsh[cur][kk][tx * 8];
            ulonglong2 bp1 = *(const ulonglong2*)&Bsh[cur][kk][tx * 8 + 4];
            unsigned long long b2[4] = { bp0.x, bp0.y, bp1.x, bp1.y };
            unsigned long long a2[8] = {
                bcast2(a0.x), bcast2(a0.y), bcast2(a0.z), bcast2(a0.w),
                bcast2(a1.x), bcast2(a1.y), bcast2(a1.z), bcast2(a1.w)
            };
            #pragma unroll
            for (int i = 0; i < 8; i++)
                #pragma unroll
                for (int j = 0; j < 4; j++)
                    fma2(acc[i][j], a2[i], b2[j]);
        }
        if (kt + 1 < T) {
            const int nxt = cur ^ 1;
            As[nxt][ak0 + 0][am] = ra0.x; As[nxt][ak0 + 1][am] = ra0.y;
            As[nxt][ak0 + 2][am] = ra0.z; As[nxt][ak0 + 3][am] = ra0.w;
            As[nxt][ak0 + 8][am] = ra1.x; As[nxt][ak0 + 9][am] = ra1.y;
            As[nxt][ak0 +10][am] = ra1.z; As[nxt][ak0 +11][am] = ra1.w;
            *(float4*)&Bsh[nxt][bk][bn]     = rb0;
            *(float4*)&Bsh[nxt][bk + 8][bn] = rb1;
        }
        __syncthreads();
    }

    #pragma unroll
    for (int i = 0; i < 8; i++) {
        const int rrow = row0 + ty * 8 + i;
        #pragma unroll
        for (int j = 0; j < 4; j++) {
            #pragma unroll
            for (int h = 0; h < 2; h++) {
                const int cc = col0 + tx * 8 + 2 * j + h;
                if (cc >= N) continue;
                float v = h ? __uint_as_float((unsigned)(acc[i][j] >> 32))
                            : __uint_as_float((unsigned)(acc[i][j]));
                if (MODE == 0) C[(size_t)rrow * N + cc] = v;
                else           C[(size_t)rrow * N + cc] = 2.f * v - ((rrow == cc) ? 1.f : 0.f);
            }
        }
    }
}

// ---------------- small kernels ----------------
__global__ void k_zero(float* p, int n) {
    int i = blockIdx.x * blockDim.x + threadIdx.x;
    if (i < n) p[i] = 0.f;
}

__global__ void k_splitA(const float* __restrict__ in, hf* __restrict__ out, int K, int total) {
    int i = blockIdx.x * blockDim.x + threadIdx.x;
    if (i >= total) return;
    int m = i / K, k = i - m * K;
    hf h, l; split2h(in[i], h, l);
    hf* p = out + (size_t)m * 2 * K;
    p[k] = h; p[K + k] = l;
}

__global__ void k_packB(const float* __restrict__ in, hf* __restrict__ out, int total) {
    int i = blockIdx.x * blockDim.x + threadIdx.x;
    if (i < total) out[i] = __float2half(in[i]);
}

__global__ void k_packB_dec(const float* __restrict__ in, hf* __restrict__ out) {
    int i = blockIdx.x * blockDim.x + threadIdx.x;
    if (i >= ROWS * DDEC) return;
    int row = i >> 7, c = i & 127;
    int n = row >> 6, b = row & 63;
    out[(size_t)n * NHBD + b * DDEC + c] = __float2half(in[i]);
}
__global__ void k_zero_go(hf* __restrict__ hB) {
    int i = blockIdx.x * blockDim.x + threadIdx.x;
    if (i >= NN * BB) return;
    int n = i >> 6, b = i & 63;
    hB[(size_t)n * NHBD + BB * DDEC + b] = __float2half(0.f);
}

__global__ void k_eW(const float* __restrict__ We, const float* __restrict__ Mem,
                     float* __restrict__ e) {
    int idx = blockIdx.x * blockDim.x + threadIdx.x;
    if (idx >= NN * 64) return;
    int n = idx >> 6, d = idx & 63;
    float s = 0.f;
    #pragma unroll
    for (int k = 0; k < 20; k++) s += We[n * 20 + k] * Mem[k * 64 + d];
    e[idx] = s;
}

__global__ void k_gsoftmax(const float* __restrict__ ea, const float* __restrict__ eb,
                           float* __restrict__ g) {
    __shared__ float er[64];
    __shared__ float buf[NN];
    __shared__ float red[128];
    int n = blockIdx.x, tid = threadIdx.x;
    if (tid < 64) er[tid] = ea[n * 64 + tid];
    __syncthreads();
    for (int m = tid; m < NN; m += 128) {
        float s = 0.f;
        #pragma unroll
        for (int d = 0; d < 64; d++) s += er[d] * eb[m * 64 + d];
        buf[m] = s > 0.f ? s : 0.f;
    }
    __syncthreads();
    float mx = -1e30f;
    for (int m = tid; m < NN; m += 128) mx = fmaxf(mx, buf[m]);
    red[tid] = mx; __syncthreads();
    for (int s = 64; s > 0; s >>= 1) { if (tid < s) red[tid] = fmaxf(red[tid], red[tid + s]); __syncthreads(); }
    mx = red[0]; __syncthreads();
    float sm = 0.f;
    for (int m = tid; m < NN; m += 128) { float e = expf(buf[m] - mx); buf[m] = e; sm += e; }
    red[tid] = sm; __syncthreads();
    for (int s = 64; s > 0; s >>= 1) { if (tid < s) red[tid] += red[tid + s]; __syncthreads(); }
    float inv = 1.f / red[0];
    for (int m = tid; m < NN; m += 128) g[n * NN + m] = buf[m] * inv;
}

__global__ void k_xT(const float* __restrict__ x, float* __restrict__ xT) {
    int idx = blockIdx.x * blockDim.x + threadIdx.x;
    if (idx >= BB * NN * LL) return;
    int l = idx % LL;
    int n = (idx / LL) % NN;
    int b = idx / (LL * NN);
    xT[(n * LL + l) * BB + b] = x[idx];
}

// fill encoder x-channels of xgE for step l (used once, l=0)
__global__ void k_fill_enc_x(hf* __restrict__ xg, const float* __restrict__ xT,
                             const float* __restrict__ GX, int l) {
    int row = blockIdx.x * blockDim.x + threadIdx.x;
    if (row >= ROWS) return;
    int n = row >> 6, b = row & 63;
    hf* p = xg + (size_t)row * KPE;
    float xv = xT[(n * LL + l) * BB + b];
    store2(p, 0, SECE, xv);
    store2(p, 195, SECE, xv);
    store2(p, 65,  SECE, GX[(size_t)(0 * NN + n) * (LL * BB) + l * BB + b]);
    store2(p, 130, SECE, GX[(size_t)(1 * NN + n) * (LL * BB) + l * BB + b]);
    store2(p, 260, SECE, GX[(size_t)(2 * NN + n) * (LL * BB) + l * BB + b]);
    store2(p, 325, SECE, GX[(size_t)(3 * NN + n) * (LL * BB) + l * BB + b]);
}

__global__ void k_fill_h_id(hf* __restrict__ xg, const float* __restrict__ h,
                            int hdshift, int sec, int off0, int off3, int total) {
    int i = blockIdx.x * blockDim.x + threadIdx.x;
    if (i >= total) return;
    int row = i >> hdshift;
    int c   = i & ((1 << hdshift) - 1);
    float v = h[i];
    hf* p = xg + (size_t)row * 2 * sec;
    store2(p, off0 + c, sec, v);
    store2(p, off3 + c, sec, v);
}

// FUSED (2/thread): zh = z*h -> xg id-blocks + hB (half2, width Ncols)
__global__ void k_zh_pack(const float* __restrict__ z, const float* __restrict__ h,
                          hf* __restrict__ xg, hf* __restrict__ hB,
                          int hdshift, int sec, int off0, int off3, int Ncols, int total2) {
    int i = blockIdx.x * blockDim.x + threadIdx.x;
    if (i >= total2) return;
    int base = i * 2;
    int row = base >> hdshift;
    int c   = base & ((1 << hdshift) - 1);
    float2 zv = *(const float2*)(z + base);
    float2 hv = *(const float2*)(h + base);
    float v0 = zv.x * hv.x, v1 = zv.y * hv.y;
    hf* p = xg + (size_t)row * 2 * sec;
    store2(p, off0 + c, sec, v0);     store2(p, off0 + c + 1, sec, v1);
    store2(p, off3 + c, sec, v0);     store2(p, off3 + c + 1, sec, v1);
    int n = row >> 6, b = row & 63;
    __half2 hv2 = __floats2half2_rn(v0, v1);
    *(__half2*)(hB + (size_t)n * Ncols + ((size_t)b << hdshift) + c) = hv2;
}

// FUSED encoder (2/thread): h' = r*h+(1-r)*hc -> h, xg id-blocks, hB,
// + NEXT-step x-channel fill (threads with c<12 each write one of 6 channels).
__global__ void k_hupd_pack(const float* __restrict__ r, const float* __restrict__ hc,
                            float* __restrict__ h,
                            hf* __restrict__ xg, hf* __restrict__ hB,
                            const float* __restrict__ xT, const float* __restrict__ GX,
                            int lnext, int total2) {
    int i = blockIdx.x * blockDim.x + threadIdx.x;
    if (i >= total2) return;
    int base = i * 2;
    int row = base >> 6;              // hdshift = 6 (RNN)
    int c   = base & 63;
    float2 rv = *(const float2*)(r + base);
    float2 hcv = *(const float2*)(hc + base);
    float2 hv = *(const float2*)(h + base);
    float hn0 = rv.x * hv.x + (1.f - rv.x) * hcv.x;
    float hn1 = rv.y * hv.y + (1.f - rv.y) * hcv.y;
    *(float2*)(h + base) = make_float2(hn0, hn1);
    hf* p = xg + (size_t)row * KPE;
    store2(p, 1 + c, SECE, hn0);    store2(p, 1 + c + 1, SECE, hn1);
    store2(p, 196 + c, SECE, hn0);  store2(p, 196 + c + 1, SECE, hn1);
    int n = row >> 6, b = row & 63;
    __half2 hv2 = __floats2half2_rn(hn0, hn1);
    *(__half2*)(hB + (size_t)n * (BB * RNN) + b * RNN + c) = hv2;
    // next-step x channels (6 per row; threads c = 0,2,4,6,8,10)
    if (lnext < LL && c < 12) {
        int idx = c >> 1;
        float v;
        int off;
        if (idx < 2) {
            v = xT[(n * LL + lnext) * BB + b];
            off = (idx == 0) ? 0 : 195;
        } else {
            int j = idx - 2;
            v = GX[(size_t)(j * NN + n) * (LL * BB) + lnext * BB + b];
            off = (j == 0) ? 65 : (j == 1) ? 130 : (j == 2) ? 260 : 325;
        }
        store2(p, off, SECE, v);
    }
}

// fill decoder go-id + ycov channels for step t (used once, t=0)
__global__ void k_fill_dec(hf* __restrict__ xg, const float* __restrict__ go,
                           const float* __restrict__ tt, int t) {
    int row = blockIdx.x * blockDim.x + threadIdx.x;
    if (row >= ROWS) return;
    int b = row & 63;
    hf* p = xg + (size_t)row * KPD;
    float gv = go[row];
    store2(p, 0,   SECD, gv);
    store2(p, 402, SECD, gv);
    #pragma unroll
    for (int c = 0; c < 5; c++) {
        float v = tt[(b * 5 + c) * HH + t];
        store2(p, 1 + c,   SECD, v); store2(p, 135 + c, SECD, v);
        store2(p, 269 + c, SECD, v); store2(p, 403 + c, SECD, v);
        store2(p, 537 + c, SECD, v); store2(p, 671 + c, SECD, v);
    }
}

__global__ void k_attn(const float* __restrict__ h, const float* __restrict__ Wq,
                       const float* __restrict__ Mem, float* __restrict__ hde) {
    __shared__ float hr[64];
    __shared__ float q[64];
    __shared__ float sc[20];
    int row = blockIdx.x, tid = threadIdx.x;
    hr[tid] = h[row * 64 + tid];
    __syncthreads();
    float s = 0.f;
    #pragma unroll
    for (int c = 0; c < 64; c++) s += hr[c] * Wq[c * 64 + tid];
    q[tid] = s;
    __syncthreads();
    if (tid < 20) {
        float v = 0.f;
        #pragma unroll
        for (int c = 0; c < 64; c++) v += q[c] * Mem[tid * 64 + c];
        sc[tid] = v;
    }
    __syncthreads();
    if (tid == 0) {
        float mx = -1e30f;
        for (int j = 0; j < 20; j++) mx = fmaxf(mx, sc[j]);
        float sm = 0.f;
        for (int j = 0; j < 20; j++) { sc[j] = expf(sc[j] - mx); sm += sc[j]; }
        float inv = 1.f / sm;
        for (int j = 0; j < 20; j++) sc[j] *= inv;
    }
    __syncthreads();
    float ha = 0.f;
    #pragma unroll
    for (int j = 0; j < 20; j++) ha += sc[j] * Mem[j * 64 + tid];
    hde[row * 128 + tid]      = hr[tid];
    hde[row * 128 + 64 + tid] = ha;
}

// FUSED decoder h update + pack + projection + go write + NEXT-step fill
__global__ void k_hupd_dec_pack(const float* __restrict__ r, const float* __restrict__ hc,
                                float* __restrict__ h, const float* __restrict__ pW,
                                const float* __restrict__ pb, float* __restrict__ go,
                                float* __restrict__ out, int t,
                                hf* __restrict__ xg, hf* __restrict__ hB,
                                const float* __restrict__ tt) {
    __shared__ float red[64];
    int row = blockIdx.x, tid = threadIdx.x;
    int c = tid * 2;
    int i = row * 128 + c;
    float2 rv = *(const float2*)(r + i);
    float2 hcv = *(const float2*)(hc + i);
    float2 hv = *(const float2*)(h + i);
    float hn0 = rv.x * hv.x + (1.f - rv.x) * hcv.x;
    float hn1 = rv.y * hv.y + (1.f - rv.y) * hcv.y;
    *(float2*)(h + i) = make_float2(hn0, hn1);
    hf* p = xg + (size_t)row * KPD;
    store2(p, 6 + c, SECD, hn0);   store2(p, 6 + c + 1, SECD, hn1);
    store2(p, 408 + c, SECD, hn0); store2(p, 408 + c + 1, SECD, hn1);
    int n = row >> 6, b = row & 63;
    __half2 hv2 = __floats2half2_rn(hn0, hn1);
    *(__half2*)(hB + (size_t)n * NHBD + b * DDEC + c) = hv2;
    float2 pw = *(const float2*)(pW + c);
    red[tid] = hn0 * pw.x + hn1 * pw.y;
    __syncthreads();
    for (int s = 32; s > 0; s >>= 1) { if (tid < s) red[tid] += red[tid + s]; __syncthreads(); }
    float g = red[0] + pb[0];
    if (tid == 0) {
        go[row] = g;
        out[(b * NN + n) * HH + t] = g;
        hB[(size_t)n * NHBD + BB * DDEC + b] = __float2half(g);   // go column for next conv
        if (t + 1 < HH) {
            store2(p, 0,   SECD, g);
            store2(p, 402, SECD, g);
        }
    }
    if (t + 1 < HH && tid < 30) {
        const int offs0[6] = {1, 135, 269, 403, 537, 671};
        int pos = tid / 5, ch = tid - pos * 5;
        float v = tt[(b * 5 + ch) * HH + (t + 1)];
        store2(p, offs0[pos] + ch, SECD, v);
    }
}

// ---------------- host side ----------------
static void bgemm_launch(int mode, const hf* A, const hf* B, void* C,
                         int M, int N, int Kp,
                         const float* bias = nullptr, float* C2 = nullptr,
                         int splitN = 0, int ldC = 0, int hdshift = 0, int sec = 0,
                         int o0 = 0, int o1 = 0, int o2 = 0, int o3 = 0)
{
    dim3 grid((N + 127) / 128, M / 128);
    switch (mode) {
        case 2: bgemm<2><<<grid, 256, SMEM_BYTES>>>(A, B, C, M, N, Kp, bias, C2, splitN, ldC, hdshift, sec, o0, o1, o2, o3); break;
        case 3: bgemm<3><<<grid, 256, SMEM_BYTES>>>(A, B, C, M, N, Kp, bias, C2, splitN, ldC, hdshift, sec, o0, o1, o2, o3); break;
        case 4: bgemm<4><<<grid, 256, SMEM_BYTES>>>(A, B, C, M, N, Kp, bias, C2, splitN, ldC, hdshift, sec, o0, o1, o2, o3); break;
    }
}

extern "C" void kernel_launch(void* const* d_in, const int* in_sizes, int n_in,
                              void* d_out, int out_size)
{
    const float* x   = (const float*)d_in[0];
    const float* tt  = (const float*)d_in[3];
    const float* Mem = (const float*)d_in[5];
    const float* Wq  = (const float*)d_in[6];
    const float* We1 = (const float*)d_in[7];
    const float* We2 = (const float*)d_in[8];
    const float* egW = (const float*)d_in[9];
    const float* egb = (const float*)d_in[10];
    const float* euW = (const float*)d_in[11];
    const float* eub = (const float*)d_in[12];
    const float* dgW = (const float*)d_in[13];
    const float* dgb = (const float*)d_in[14];
    const float* duW = (const float*)d_in[15];
    const float* dub = (const float*)d_in[16];
    const float* pW  = (const float*)d_in[17];
    const float* pb  = (const float*)d_in[18];
    float* out = (float*)d_out;

    cudaFuncSetAttribute(bgemm<2>, cudaFuncAttributeMaxDynamicSharedMemorySize, SMEM_BYTES);
    cudaFuncSetAttribute(bgemm<3>, cudaFuncAttributeMaxDynamicSharedMemorySize, SMEM_BYTES);
    cudaFuncSetAttribute(bgemm<4>, cudaFuncAttributeMaxDynamicSharedMemorySize, SMEM_BYTES);

    float *S, *e1, *e2, *xT, *GX, *henc, *hdec, *z, *r, *hc, *go;
    hf *Sbig, *hB, *xgE, *xgD, *egWB, *euWB, *dgWB, *duWB;
    cudaGetSymbolAddress((void**)&S,    g_S);
    cudaGetSymbolAddress((void**)&e1,   g_e1);
    cudaGetSymbolAddress((void**)&e2,   g_e2);
    cudaGetSymbolAddress((void**)&xT,   g_xT);
    cudaGetSymbolAddress((void**)&GX,   g_GX);
    cudaGetSymbolAddress((void**)&henc, g_henc);
    cudaGetSymbolAddress((void**)&hdec, g_hdec);
    cudaGetSymbolAddress((void**)&z,    g_z);
    cudaGetSymbolAddress((void**)&r,    g_r);
    cudaGetSymbolAddress((void**)&hc,   g_hc);
    cudaGetSymbolAddress((void**)&go,   g_go);
    cudaGetSymbolAddress((void**)&Sbig, g_Sbig);
    cudaGetSymbolAddress((void**)&hB,   g_hB);
    cudaGetSymbolAddress((void**)&xgE,  g_xgE);
    cudaGetSymbolAddress((void**)&xgD,  g_xgD);
    cudaGetSymbolAddress((void**)&egWB, g_egWB);
    cudaGetSymbolAddress((void**)&euWB, g_euWB);
    cudaGetSymbolAddress((void**)&dgWB, g_dgWB);
    cudaGetSymbolAddress((void**)&duWB, g_duWB);

    // --- weight packs ---
    k_packB<<<(KENC * 128 + 255) / 256, 256>>>(egW, egWB, KENC * 128);
    k_packB<<<(KENC * 64  + 255) / 256, 256>>>(euW, euWB, KENC * 64);
    k_packB<<<(KDEC * 256 + 255) / 256, 256>>>(dgW, dgWB, KDEC * 256);
    k_packB<<<(KDEC * 128 + 255) / 256, 256>>>(duW, duWB, KDEC * 128);

    // --- supports (fp32) ---
    k_eW<<<(NN * 64 + 255) / 256, 256>>>(We1, Mem, e1);
    k_eW<<<(NN * 64 + 255) / 256, 256>>>(We2, Mem, e2);
    k_gsoftmax<<<NN, 128>>>(e1, e2, S);
    k_gsoftmax<<<NN, 128>>>(e2, e1, S + 2 * NN * NN);
    {
        dim3 g1(NN / 128, NN / 128);
        sgemm<1><<<g1, 256>>>(S,               S,               S + 1 * NN * NN, NN, NN, NN);
        sgemm<1><<<g1, 256>>>(S + 2 * NN * NN, S + 2 * NN * NN, S + 3 * NN * NN, NN, NN, NN);
    }
    k_splitA<<<(4 * NN * NN + 255) / 256, 256>>>(S, Sbig, NN, 4 * NN * NN);

    // --- encoder x precompute (fp32) ---
    k_xT<<<(BB * NN * LL + 255) / 256, 256>>>(x, xT);
    {
        dim3 g2((LL * BB + 127) / 128, 4 * NN / 128);
        sgemm<0><<<g2, 256>>>(S, xT, GX, 4 * NN, LL * BB, NN);
    }

    // --- init states ---
    k_zero<<<(ROWS * RNN + 255) / 256, 256>>>(henc, ROWS * RNN);
    k_zero<<<(ROWS + 255) / 256, 256>>>(go, ROWS);
    k_fill_h_id<<<(ROWS * RNN) / 256, 256>>>(xgE, henc, 6, SECE, 1, 196, ROWS * RNN);
    k_packB<<<(ROWS * RNN + 255) / 256, 256>>>(henc, hB, ROWS * RNN);
    k_fill_enc_x<<<ROWS / 256, 256>>>(xgE, xT, GX, 0);   // step-0 fill (later fused)

    // --- encoder ---
    for (int l = 0; l < LL; l++) {
        bgemm_launch(4, Sbig, hB, xgE, 4 * NN, BB * RNN, KGC,
                     nullptr, nullptr, 0, 0, 6, SECE, 66, 131, 261, 326);
        bgemm_launch(2, xgE, egWB, z, ROWS, 2 * RNN, KPE, egb, r, RNN);
        k_zh_pack<<<(ROWS * RNN / 2) / 256, 256>>>(z, henc, xgE, hB, 6, SECE, 1, 196, BB * RNN, ROWS * RNN / 2);
        bgemm_launch(4, Sbig, hB, xgE, 4 * NN, BB * RNN, KGC,
                     nullptr, nullptr, 0, 0, 6, SECE, 66, 131, 261, 326);
        bgemm_launch(3, xgE, euWB, hc, ROWS, RNN, KPE, eub, nullptr, 0, RNN);
        k_hupd_pack<<<(ROWS * RNN / 2) / 256, 256>>>(r, hc, henc, xgE, hB, xT, GX, l + 1, ROWS * RNN / 2);
    }

    // --- memory attention -> decoder initial hidden ---
    k_attn<<<ROWS, 64>>>(henc, Wq, Mem, hdec);
    k_fill_h_id<<<(ROWS * DDEC) / 256, 256>>>(xgD, hdec, 7, SECD, 6, 408, ROWS * DDEC);
    k_packB_dec<<<(ROWS * DDEC + 255) / 256, 256>>>(hdec, hB);
    k_zero_go<<<(NN * BB + 255) / 256, 256>>>(hB);
    k_fill_dec<<<ROWS / 256, 256>>>(xgD, go, tt, 0);   // step-0 fill (later steps fused)

    // --- decoder ---
    for (int t = 0; t < HH; t++) {
        bgemm_launch(4, Sbig, hB, xgD, 4 * NN, NHBD, KGC,
                     nullptr, nullptr, BB * DDEC, 0, 7, SECD, 140, 274, 542, 676);
        bgemm_launch(2, xgD, dgWB, z, ROWS, 2 * DDEC, KPD, dgb, r, DDEC);
        k_zh_pack<<<(ROWS * DDEC / 2) / 256, 256>>>(z, hdec, xgD, hB, 7, SECD, 6, 408, NHBD, ROWS * DDEC / 2);
        bgemm_launch(4, Sbig, hB, xgD, 4 * NN, NHBD, KGC,
                     nullptr, nullptr, BB * DDEC, 0, 7, SECD, 140, 274, 542, 676);
        bgemm_launch(3, xgD, duWB, hc, ROWS, DDEC, KPD, dub, nullptr, 0, DDEC);
        k_hupd_dec_pack<<<ROWS, 64>>>(r, hc, hdec, pW, pb, go, out, t, xgD, hB, tt);
    }
}